// round 12
// baseline (speedup 1.0000x reference)
#include <cuda_runtime.h>
#include <cuda_bf16.h>
#include <stdint.h>
#include <math.h>

typedef unsigned int u32;
typedef unsigned short u16;

#define MAXN 100096
#define MAXE 1600000
#define F    128

// ---------------- device scratch ------------------------------------------------
__device__ int   g_cnt[MAXN];
__device__ int   g_rowptr[MAXN + 1];
__device__ int   g_cursor[MAXN];
__device__ int   g_col[MAXE];
__device__ float g_dis[MAXN];

__device__ float g_t0[MAXN * F];
__device__ float g_t1[MAXN * F];
__device__ float g_t2[MAXN * F];
__device__ float g_env[MAXN * F];
__device__ float g_inv[MAXN * F];

// pre-split weights: 7 blocks of [n=128][k=128] bf16 (transposed for B operand)
__device__ __align__(16) u16 g_wh[7 * 16384];
__device__ __align__(16) u16 g_wl[7 * 16384];

// CKA moments
#define CKA_SXX 0
#define CKA_SXY 16384
#define CKA_SYY 32768
#define CKA_SX  49152
#define CKA_SY  49280
#define CKA_TOT 49408
__device__ float g_cka[CKA_TOT];

// ================= helpers ======================================================
__device__ __forceinline__ u32 smem_u32(const void* p) {
    u32 a;
    asm("{ .reg .u64 t; cvta.to.shared.u64 t, %1; cvt.u32.u64 %0, t; }" : "=r"(a) : "l"(p));
    return a;
}
__device__ __forceinline__ void ldm_x4(u32& r0, u32& r1, u32& r2, u32& r3, u32 addr) {
    asm volatile("ldmatrix.sync.aligned.m8n8.x4.shared.b16 {%0,%1,%2,%3}, [%4];"
                 : "=r"(r0), "=r"(r1), "=r"(r2), "=r"(r3) : "r"(addr));
}
__device__ __forceinline__ void mma16816(float* c, const u32* a, u32 b0, u32 b1) {
    asm volatile(
        "mma.sync.aligned.m16n8k16.row.col.f32.bf16.bf16.f32 "
        "{%0,%1,%2,%3}, {%4,%5,%6,%7}, {%8,%9}, {%0,%1,%2,%3};"
        : "+f"(c[0]), "+f"(c[1]), "+f"(c[2]), "+f"(c[3])
        : "r"(a[0]), "r"(a[1]), "r"(a[2]), "r"(a[3]), "r"(b0), "r"(b1));
}
__device__ __forceinline__ u16 f2bf(float x) {
    return __bfloat16_as_ushort(__float2bfloat16_rn(x));
}
__device__ __forceinline__ float bf2f(u16 u) {
    return __bfloat162float(__ushort_as_bfloat16(u));
}

// ---------------- prep: split weights + zero cnt + zero cka (runs FIRST) ---------
__global__ void k_prep(const float* W_ir1, const float* W_ir2, const float* W_g1,
                       const float* W_g2, const float* W_d1, const float* W_d2, int n)
{
    int idx = blockIdx.x * blockDim.x + threadIdx.x;
    if (idx < 7 * 16384) {
        int w = idx >> 14;
        int rem = idx & 16383;
        int nn = rem >> 7;
        int k = rem & 127;
        float v;
        switch (w) {
            case 0: v = W_ir1[k * 128 + nn]; break;
            case 1: v = W_ir2[k * 128 + nn]; break;
            case 2: v = W_g1[k * 128 + nn];  break;
            case 3: v = W_g2[k * 128 + nn];  break;
            case 4: v = W_d1[k * 128 + nn];  break;
            case 5: v = W_d1[(k + 128) * 128 + nn]; break;
            default: v = W_d2[k * 128 + nn]; break;
        }
        u16 h = f2bf(v);
        u16 l = f2bf(v - bf2f(h));
        g_wh[idx] = h;
        g_wl[idx] = l;
        return;
    }
    idx -= 7 * 16384;
    if (idx < n) { g_cnt[idx] = 0; return; }
    idx -= n;
    if (idx < CKA_TOT) g_cka[idx] = 0.f;
}

// ---------------- CSR kernels ----------------------------------------------------
__global__ void k_count(const int* __restrict__ ei, int E) {
    int e = blockIdx.x * blockDim.x + threadIdx.x;
    if (e < E) atomicAdd(&g_cnt[ei[E + e]], 1);
}

__global__ __launch_bounds__(1024) void k_scan1(int n) {
    __shared__ int s[1024];
    __shared__ int prevs;
    const int b = blockIdx.x, t = threadIdx.x;
    const int base = b * 1024;
    int acc = 0;
    for (int i = t; i < base; i += 1024) acc += g_cnt[i];
    s[t] = acc;
    __syncthreads();
    for (int o = 512; o > 0; o >>= 1) {
        if (t < o) s[t] += s[t + o];
        __syncthreads();
    }
    if (t == 0) prevs = s[0];
    __syncthreads();
    int prev = prevs;
    __syncthreads();
    int i = base + t;
    int v = (i < n) ? g_cnt[i] : 0;
    s[t] = v;
    __syncthreads();
    for (int o = 1; o < 1024; o <<= 1) {
        int u = (t >= o) ? s[t - o] : 0;
        __syncthreads();
        s[t] += u;
        __syncthreads();
    }
    if (i < n) {
        int ex = prev + s[t] - v;
        g_rowptr[i] = ex;
        g_cursor[i] = ex;
        g_dis[i] = rsqrtf((float)(v + 1));
        if (i == n - 1) g_rowptr[n] = ex + v;
    }
}

__global__ void k_fill(const int* __restrict__ ei, int E) {
    int e = blockIdx.x * blockDim.x + threadIdx.x;
    if (e < E) {
        int src = ei[e];
        int dst = ei[E + e];
        int p = atomicAdd(&g_cursor[dst], 1);
        g_col[p] = src;
    }
}

// ---------------- AGG variants ----------------------------------------------------
// dis inline (hp raw): out[v] = act(dis[v]*(sum dis[u]*hp[u] + dis[v]*hp[v]) + b)
__global__ void k_agg_d(const float* __restrict__ hp, const float* __restrict__ bias,
                        float* __restrict__ out, int n, int act)
{
    int gw = (blockIdx.x * blockDim.x + threadIdx.x) >> 5;
    int lane = threadIdx.x & 31;
    if (gw >= n) return;
    const float4* h4 = (const float4*)hp;
    float dv = g_dis[gw];
    float4 self = h4[gw * 32 + lane];
    float4 a;
    a.x = dv * self.x; a.y = dv * self.y; a.z = dv * self.z; a.w = dv * self.w;
    int s = g_rowptr[gw], e = g_rowptr[gw + 1];
    int i = s;
    for (; i + 2 <= e; i += 2) {
        int u0 = g_col[i], u1 = g_col[i + 1];
        float d0 = g_dis[u0], d1 = g_dis[u1];
        float4 v0 = __ldg(&h4[u0 * 32 + lane]);
        float4 v1 = __ldg(&h4[u1 * 32 + lane]);
        a.x = fmaf(d0, v0.x, a.x); a.y = fmaf(d0, v0.y, a.y);
        a.z = fmaf(d0, v0.z, a.z); a.w = fmaf(d0, v0.w, a.w);
        a.x = fmaf(d1, v1.x, a.x); a.y = fmaf(d1, v1.y, a.y);
        a.z = fmaf(d1, v1.z, a.z); a.w = fmaf(d1, v1.w, a.w);
    }
    if (i < e) {
        int u = g_col[i];
        float du = g_dis[u];
        float4 v = __ldg(&h4[u * 32 + lane]);
        a.x = fmaf(du, v.x, a.x); a.y = fmaf(du, v.y, a.y);
        a.z = fmaf(du, v.z, a.z); a.w = fmaf(du, v.w, a.w);
    }
    float4 b = ((const float4*)bias)[lane];
    float4 r;
    r.x = fmaf(dv, a.x, b.x);
    r.y = fmaf(dv, a.y, b.y);
    r.z = fmaf(dv, a.z, b.z);
    r.w = fmaf(dv, a.w, b.w);
    if (act == 1) {
        r.x = fmaxf(r.x, 0.f); r.y = fmaxf(r.y, 0.f);
        r.z = fmaxf(r.z, 0.f); r.w = fmaxf(r.w, 0.f);
    } else if (act == 2) {
        r.x = tanhf(r.x); r.y = tanhf(r.y);
        r.z = tanhf(r.z); r.w = tanhf(r.w);
    }
    ((float4*)out)[gw * 32 + lane] = r;
}

// hp pre-scaled by dis: out[v] = act(dis[v]*(sum hp[u] + hp[v]) + b)
__global__ void k_agg(const float* __restrict__ hp, const float* __restrict__ bias,
                      float* __restrict__ out, int n, int act)
{
    int gw = (blockIdx.x * blockDim.x + threadIdx.x) >> 5;
    int lane = threadIdx.x & 31;
    if (gw >= n) return;
    const float4* h4 = (const float4*)hp;
    float4 a = h4[gw * 32 + lane];
    int s = g_rowptr[gw], e = g_rowptr[gw + 1];
    int i = s;
    for (; i + 2 <= e; i += 2) {
        int u0 = g_col[i], u1 = g_col[i + 1];
        float4 v0 = __ldg(&h4[u0 * 32 + lane]);
        float4 v1 = __ldg(&h4[u1 * 32 + lane]);
        a.x += v0.x + v1.x; a.y += v0.y + v1.y;
        a.z += v0.z + v1.z; a.w += v0.w + v1.w;
    }
    if (i < e) {
        int u = g_col[i];
        float4 v = __ldg(&h4[u * 32 + lane]);
        a.x += v.x; a.y += v.y; a.z += v.z; a.w += v.w;
    }
    float d = g_dis[gw];
    float4 b = ((const float4*)bias)[lane];
    float4 r;
    r.x = fmaf(d, a.x, b.x);
    r.y = fmaf(d, a.y, b.y);
    r.z = fmaf(d, a.z, b.z);
    r.w = fmaf(d, a.w, b.w);
    if (act == 1) {
        r.x = fmaxf(r.x, 0.f); r.y = fmaxf(r.y, 0.f);
        r.z = fmaxf(r.z, 0.f); r.w = fmaxf(r.w, 0.f);
    } else if (act == 2) {
        r.x = tanhf(r.x); r.y = tanhf(r.y);
        r.z = tanhf(r.z); r.w = tanhf(r.w);
    }
    ((float4*)out)[gw * 32 + lane] = r;
}

__global__ void k_agg_ln(const float* __restrict__ hp, const float* __restrict__ bias,
                         const float* __restrict__ lng, const float* __restrict__ lnb,
                         float* __restrict__ out, int n)
{
    int gw = (blockIdx.x * blockDim.x + threadIdx.x) >> 5;
    int lane = threadIdx.x & 31;
    if (gw >= n) return;
    const float4* h4 = (const float4*)hp;
    float4 a = h4[gw * 32 + lane];
    int s = g_rowptr[gw], e = g_rowptr[gw + 1];
    int i = s;
    for (; i + 2 <= e; i += 2) {
        int u0 = g_col[i], u1 = g_col[i + 1];
        float4 v0 = __ldg(&h4[u0 * 32 + lane]);
        float4 v1 = __ldg(&h4[u1 * 32 + lane]);
        a.x += v0.x + v1.x; a.y += v0.y + v1.y;
        a.z += v0.z + v1.z; a.w += v0.w + v1.w;
    }
    if (i < e) {
        int u = g_col[i];
        float4 v = __ldg(&h4[u * 32 + lane]);
        a.x += v.x; a.y += v.y; a.z += v.z; a.w += v.w;
    }
    float d = g_dis[gw];
    float4 b = ((const float4*)bias)[lane];
    float4 v;
    v.x = fmaf(d, a.x, b.x);
    v.y = fmaf(d, a.y, b.y);
    v.z = fmaf(d, a.z, b.z);
    v.w = fmaf(d, a.w, b.w);
    float sum = v.x + v.y + v.z + v.w;
#pragma unroll
    for (int o = 16; o; o >>= 1) sum += __shfl_xor_sync(0xffffffffu, sum, o);
    float mu = sum * (1.f / 128.f);
    float dx = v.x - mu, dy = v.y - mu, dz = v.z - mu, dw = v.w - mu;
    float qq = dx * dx + dy * dy + dz * dz + dw * dw;
#pragma unroll
    for (int o = 16; o; o >>= 1) qq += __shfl_xor_sync(0xffffffffu, qq, o);
    float rs = rsqrtf(qq * (1.f / 128.f) + 1e-5f);
    float4 gg = ((const float4*)lng)[lane];
    float4 bb = ((const float4*)lnb)[lane];
    float* o = out + (size_t)gw * 128 + lane * 4;
    o[0] = dx * rs * gg.x + bb.x;
    o[1] = dy * rs * gg.y + bb.y;
    o[2] = dz * rs * gg.z + bb.z;
    o[3] = dw * rs * gg.w + bb.w;
}

// ---------------- tensor-core GEMM, 64-row tiles, 2 CTAs/SM -------------------------
#define APITCH 272
#define A64_HI 0
#define A64_LO 17408
#define CPB    144
#define B64_HI 34816
#define B64_LO 53248
#define GM_SMEM 71680

__global__ void __launch_bounds__(256, 2) k_gemm_m(
    const float* __restrict__ A0, const float* __restrict__ A1, int npass,
    int wA, int wB, int nw,
    const float* __restrict__ biasA, const float* __restrict__ biasB,
    const float* __restrict__ dis,
    float* __restrict__ outA, float* __restrict__ outB, int n)
{
    extern __shared__ char sm[];
    const u32 sb = smem_u32(sm);
    const int tid = threadIdx.x;
    const int wid = tid >> 5;
    const int lane = tid & 31;
    const int br = blockIdx.x * 64;

    const int m0 = (wid & 1) * 32;
    const int n0 = (wid >> 1) * 32;
    const int q = lane >> 3, r8 = lane & 7;
    const u32 aOff = (u32)(m0 + r8 + ((q & 1) << 3)) * APITCH + (u32)(((q >> 1) << 3) << 1);
    const u32 bOff = (u32)(n0 + r8 + ((q >> 1) << 3)) * CPB + (u32)(((q & 1) << 3) << 1);
    const int g4 = lane >> 2, t4 = lane & 3;

    float c[2][4][4];
#pragma unroll
    for (int i = 0; i < 2; ++i)
#pragma unroll
        for (int j = 0; j < 4; ++j)
#pragma unroll
            for (int k = 0; k < 4; ++k) c[i][j][k] = 0.f;

    for (int p = 0; p < npass; ++p) {
        const float* A = p ? A1 : A0;
        if (p) __syncthreads();
        for (int idx = tid; idx < 4096; idx += 256) {
            int m = idx >> 6;
            int kp = (idx & 63) * 2;
            int row = br + m;
            float2 v = make_float2(0.f, 0.f);
            if (row < n) v = *(const float2*)(A + (size_t)row * 128 + kp);
            u16 hx = f2bf(v.x), hy = f2bf(v.y);
            u16 lx = f2bf(v.x - bf2f(hx)), ly = f2bf(v.y - bf2f(hy));
            u32 o = (u32)m * APITCH + (u32)kp * 2;
            *(u32*)(sm + A64_HI + o) = (u32)hx | ((u32)hy << 16);
            *(u32*)(sm + A64_LO + o) = (u32)lx | ((u32)ly << 16);
        }

        for (int w = 0; w < nw; ++w) {
            int wsel = (nw == 2) ? (w ? wB : wA) : (wA + p);
            const u16* wh = g_wh + (size_t)wsel * 16384;
            const u16* wl = g_wl + (size_t)wsel * 16384;
            for (int ch = 0; ch < 2; ++ch) {
                __syncthreads();
                const int k0 = ch * 64;
                for (int idx = tid; idx < 1024; idx += 256) {
                    int nn = idx >> 3;
                    int v = idx & 7;
                    uint4 h = *(const uint4*)(wh + nn * 128 + k0 + v * 8);
                    uint4 l = *(const uint4*)(wl + nn * 128 + k0 + v * 8);
                    u32 o = (u32)nn * CPB + (u32)v * 16;
                    *(uint4*)(sm + B64_HI + o) = h;
                    *(uint4*)(sm + B64_LO + o) = l;
                }
                __syncthreads();

                const u32 aB[3] = { sb + A64_HI + aOff + (u32)ch * 128,
                                    sb + A64_HI + aOff + (u32)ch * 128,
                                    sb + A64_LO + aOff + (u32)ch * 128 };
                const u32 bB[3] = { sb + B64_HI + bOff, sb + B64_LO + bOff, sb + B64_HI + bOff };
#pragma unroll
                for (int t = 0; t < 3; ++t) {
#pragma unroll
                    for (int kk = 0; kk < 4; ++kk) {
                        u32 a[2][4];
#pragma unroll
                        for (int mi = 0; mi < 2; ++mi)
                            ldm_x4(a[mi][0], a[mi][1], a[mi][2], a[mi][3],
                                   aB[t] + (u32)mi * 16 * APITCH + (u32)kk * 32);
                        u32 bb[8];
                        ldm_x4(bb[0], bb[1], bb[2], bb[3], bB[t] + (u32)kk * 32);
                        ldm_x4(bb[4], bb[5], bb[6], bb[7], bB[t] + 16 * CPB + (u32)kk * 32);
#pragma unroll
                        for (int mi = 0; mi < 2; ++mi)
#pragma unroll
                            for (int ni = 0; ni < 4; ++ni)
                                mma16816(c[mi][ni], a[mi], bb[2 * ni], bb[2 * ni + 1]);
                    }
                }
            }
            if (nw == 2) {
                const float* bias = w ? biasB : biasA;
                float* out = w ? outB : outA;
#pragma unroll
                for (int mi = 0; mi < 2; ++mi) {
                    int row0 = br + m0 + mi * 16 + g4;
                    int row1 = row0 + 8;
#pragma unroll
                    for (int ni = 0; ni < 4; ++ni) {
                        int col = n0 + ni * 8 + 2 * t4;
                        float bx = bias ? bias[col] : 0.f;
                        float by = bias ? bias[col + 1] : 0.f;
                        float2 v0 = make_float2(c[mi][ni][0] + bx, c[mi][ni][1] + by);
                        float2 v1 = make_float2(c[mi][ni][2] + bx, c[mi][ni][3] + by);
                        if (bias) {
                            v0.x = fmaxf(v0.x, 0.f); v0.y = fmaxf(v0.y, 0.f);
                            v1.x = fmaxf(v1.x, 0.f); v1.y = fmaxf(v1.y, 0.f);
                        }
                        if (row0 < n) *(float2*)(out + (size_t)row0 * 128 + col) = v0;
                        if (row1 < n) *(float2*)(out + (size_t)row1 * 128 + col) = v1;
                    }
                }
#pragma unroll
                for (int i = 0; i < 2; ++i)
#pragma unroll
                    for (int j = 0; j < 4; ++j)
#pragma unroll
                        for (int k = 0; k < 4; ++k) c[i][j][k] = 0.f;
            }
        }
    }

    if (nw == 1) {
#pragma unroll
        for (int mi = 0; mi < 2; ++mi) {
            int row0 = br + m0 + mi * 16 + g4;
            int row1 = row0 + 8;
            if (row0 < n) {
                float d = dis[row0];
#pragma unroll
                for (int ni = 0; ni < 4; ++ni)
                    *(float2*)(outA + (size_t)row0 * 128 + n0 + ni * 8 + 2 * t4) =
                        make_float2(d * c[mi][ni][0], d * c[mi][ni][1]);
            }
            if (row1 < n) {
                float d = dis[row1];
#pragma unroll
                for (int ni = 0; ni < 4; ++ni)
                    *(float2*)(outA + (size_t)row1 * 128 + n0 + ni * 8 + 2 * t4) =
                        make_float2(d * c[mi][ni][2], d * c[mi][ni][3]);
            }
        }
    }
}

// ---------------- CKA --------------------------------------------------------------
__global__ void k_colsum(const float* __restrict__ X, float* __restrict__ s, int n)
{
    int j = threadIdx.x;
    int r0 = blockIdx.x * 256;
    int r1 = r0 + 256; if (r1 > n) r1 = n;
    float acc = 0.f;
    for (int r = r0; r < r1; ++r) acc += X[r * 128 + j];
    atomicAdd(&s[j], acc);
}

#define TPITCH 272
#define TBYTES (128 * TPITCH)
#define OFF_AHI 0
#define OFF_ALO TBYTES
#define OFF_BHI (2 * TBYTES)
#define OFF_BLO (3 * TBYTES)
#define ATB_SMEM (4 * TBYTES)

__global__ __launch_bounds__(256)
void k_atb_tc(const float* __restrict__ X, const float* __restrict__ Y,
              float* __restrict__ S, int n)
{
    extern __shared__ char sm[];
    const u32 sb = smem_u32(sm);
    const int tid = threadIdx.x;
    const int wid = tid >> 5;
    const int lane = tid & 31;

    const int m0 = (wid & 1) * 64;
    const int n0 = (wid >> 1) * 32;
    const int q = lane >> 3, r8 = lane & 7;
    const u32 aOff = (u32)(m0 + r8 + ((q & 1) << 3)) * TPITCH + (u32)(((q >> 1) << 3) << 1);
    const u32 bOff = (u32)(n0 + r8 + ((q >> 1) << 3)) * TPITCH + (u32)(((q & 1) << 3) << 1);

    float c[4][4][4];
#pragma unroll
    for (int i = 0; i < 4; ++i)
#pragma unroll
        for (int j = 0; j < 4; ++j)
#pragma unroll
            for (int k = 0; k < 4; ++k) c[i][j][k] = 0.f;

    bool first = true;
    for (int r0 = blockIdx.x * 128; r0 < n; r0 += gridDim.x * 128) {
        if (!first) __syncthreads();
        first = false;

        for (int idx = tid; idx < 8192; idx += 256) {
            int rl = idx >> 6;
            int fp = (idx & 63) * 2;
            int row = r0 + rl;
            float2 v = make_float2(0.f, 0.f);
            if (row < n) v = *(const float2*)(X + (size_t)row * 128 + fp);
            u16 hx = f2bf(v.x), hy = f2bf(v.y);
            u16 lx = f2bf(v.x - bf2f(hx)), ly = f2bf(v.y - bf2f(hy));
            u32 o0 = (u32)fp * TPITCH + (u32)rl * 2;
            u32 o1 = o0 + TPITCH;
            *(u16*)(sm + OFF_AHI + o0) = hx;
            *(u16*)(sm + OFF_AHI + o1) = hy;
            *(u16*)(sm + OFF_ALO + o0) = lx;
            *(u16*)(sm + OFF_ALO + o1) = ly;
        }
        for (int idx = tid; idx < 8192; idx += 256) {
            int rl = idx >> 6;
            int fp = (idx & 63) * 2;
            int row = r0 + rl;
            float2 v = make_float2(0.f, 0.f);
            if (row < n) v = *(const float2*)(Y + (size_t)row * 128 + fp);
            u16 hx = f2bf(v.x), hy = f2bf(v.y);
            u16 lx = f2bf(v.x - bf2f(hx)), ly = f2bf(v.y - bf2f(hy));
            u32 o0 = (u32)fp * TPITCH + (u32)rl * 2;
            u32 o1 = o0 + TPITCH;
            *(u16*)(sm + OFF_BHI + o0) = hx;
            *(u16*)(sm + OFF_BHI + o1) = hy;
            *(u16*)(sm + OFF_BLO + o0) = lx;
            *(u16*)(sm + OFF_BLO + o1) = ly;
        }
        __syncthreads();

        const u32 aB[3] = { sb + OFF_AHI + aOff, sb + OFF_AHI + aOff, sb + OFF_ALO + aOff };
        const u32 bB[3] = { sb + OFF_BHI + bOff, sb + OFF_BLO + bOff, sb + OFF_BHI + bOff };
#pragma unroll
        for (int t = 0; t < 3; ++t) {
#pragma unroll
            for (int kk = 0; kk < 8; ++kk) {
                u32 a[4][4];
#pragma unroll
                for (int mi = 0; mi < 4; ++mi)
                    ldm_x4(a[mi][0], a[mi][1], a[mi][2], a[mi][3],
                           aB[t] + (u32)mi * 16 * TPITCH + (u32)kk * 32);
                u32 bb[8];
                ldm_x4(bb[0], bb[1], bb[2], bb[3], bB[t] + (u32)kk * 32);
                ldm_x4(bb[4], bb[5], bb[6], bb[7], bB[t] + 16 * TPITCH + (u32)kk * 32);
#pragma unroll
                for (int mi = 0; mi < 4; ++mi)
#pragma unroll
                    for (int ni = 0; ni < 4; ++ni)
                        mma16816(c[mi][ni], a[mi], bb[2 * ni], bb[2 * ni + 1]);
            }
        }
    }

    const int g = lane >> 2, t4 = lane & 3;
#pragma unroll
    for (int mi = 0; mi < 4; ++mi) {
        int fi0 = m0 + mi * 16 + g;
        int fi1 = fi0 + 8;
#pragma unroll
        for (int ni = 0; ni < 4; ++ni) {
            int fj = n0 + ni * 8 + 2 * t4;
            atomicAdd(&S[fi0 * 128 + fj],     c[mi][ni][0]);
            atomicAdd(&S[fi0 * 128 + fj + 1], c[mi][ni][1]);
            atomicAdd(&S[fi1 * 128 + fj],     c[mi][ni][2]);
            atomicAdd(&S[fi1 * 128 + fj + 1], c[mi][ni][3]);
        }
    }
}

__global__ void k_cka(const float* __restrict__ cka, float* __restrict__ out,
                      int off, float fn)
{
    __shared__ float r0[256], r1[256], r2[256];
    const float* Sxx = cka + CKA_SXX;
    const float* Sxy = cka + CKA_SXY;
    const float* Syy = cka + CKA_SYY;
    const float* sx  = cka + CKA_SX;
    const float* sy  = cka + CKA_SY;
    int t = threadIdx.x;
    float hs = 0.f, nx = 0.f, ny = 0.f;
    float inv_n = 1.f / fn;
    for (int idx = t; idx < 16384; idx += 256) {
        int i = idx >> 7, j = idx & 127;
        float mxi = sx[i] * inv_n, mxj = sx[j] * inv_n;
        float myi = sy[i] * inv_n, myj = sy[j] * inv_n;
        float cxy = Sxy[idx] - fn * mxi * myj;
        float cxx = Sxx[idx] - fn * mxi * mxj;
        float cyy = Syy[idx] - fn * myi * myj;
        hs += cxy * cxy;
        nx += cxx * cxx;
        ny += cyy * cyy;
    }
    r0[t] = hs; r1[t] = nx; r2[t] = ny;
    __syncthreads();
    for (int o = 128; o > 0; o >>= 1) {
        if (t < o) { r0[t] += r0[t + o]; r1[t] += r1[t + o]; r2[t] += r2[t + o]; }
        __syncthreads();
    }
    if (t == 0) {
        float val = r0[0] / (sqrtf(r1[0]) * sqrtf(r2[0]));
        for (int i = 0; i < off; ++i) out[i] = val;
    }
}

// ---------------- host ---------------------------------------------------------------
extern "C" void kernel_launch(void* const* d_in, const int* in_sizes, int n_in,
                              void* d_out, int out_size)
{
    const float* x     = (const float*)d_in[0];
    const int*   ei    = (const int*)  d_in[1];
    const float* W_ir1 = (const float*)d_in[2];
    const float* b_ir1 = (const float*)d_in[3];
    const float* W_ir2 = (const float*)d_in[4];
    const float* b_ir2 = (const float*)d_in[5];
    const float* W_g1  = (const float*)d_in[6];
    const float* b_g1  = (const float*)d_in[7];
    const float* W_g2  = (const float*)d_in[8];
    const float* b_g2  = (const float*)d_in[9];
    const float* W_d1  = (const float*)d_in[10];
    const float* b_d1  = (const float*)d_in[11];
    const float* W_d2  = (const float*)d_in[12];
    const float* b_d2  = (const float*)d_in[13];
    const float* ln_g  = (const float*)d_in[14];
    const float* ln_b  = (const float*)d_in[15];

    const int N = in_sizes[0] / F;
    const int E = in_sizes[1] / 2;

    float *t0, *t1, *t2, *envp, *invp, *disp, *cka;
    cudaGetSymbolAddress((void**)&t0,   g_t0);
    cudaGetSymbolAddress((void**)&t1,   g_t1);
    cudaGetSymbolAddress((void**)&t2,   g_t2);
    cudaGetSymbolAddress((void**)&envp, g_env);
    cudaGetSymbolAddress((void**)&invp, g_inv);
    cudaGetSymbolAddress((void**)&disp, g_dis);
    cudaGetSymbolAddress((void**)&cka,  g_cka);

    static cudaStream_t s1 = 0, s2 = 0;
    static cudaEvent_t eP = 0, eFill = 0, eG12 = 0, eIr1 = 0, eG1 = 0, eG3 = 0,
                       eG4 = 0, eEnv = 0, eInv = 0, eG5 = 0, eDec1 = 0, eG6 = 0,
                       eLn = 0, eS2 = 0;
    if (!s1) {
        cudaStreamCreateWithFlags(&s1, cudaStreamNonBlocking);
        cudaStreamCreateWithFlags(&s2, cudaStreamNonBlocking);
        cudaEventCreateWithFlags(&eP,   cudaEventDisableTiming);
        cudaEventCreateWithFlags(&eFill,cudaEventDisableTiming);
        cudaEventCreateWithFlags(&eG12, cudaEventDisableTiming);
        cudaEventCreateWithFlags(&eIr1, cudaEventDisableTiming);
        cudaEventCreateWithFlags(&eG1,  cudaEventDisableTiming);
        cudaEventCreateWithFlags(&eG3,  cudaEventDisableTiming);
        cudaEventCreateWithFlags(&eG4,  cudaEventDisableTiming);
        cudaEventCreateWithFlags(&eEnv, cudaEventDisableTiming);
        cudaEventCreateWithFlags(&eInv, cudaEventDisableTiming);
        cudaEventCreateWithFlags(&eG5,  cudaEventDisableTiming);
        cudaEventCreateWithFlags(&eDec1,cudaEventDisableTiming);
        cudaEventCreateWithFlags(&eG6,  cudaEventDisableTiming);
        cudaEventCreateWithFlags(&eLn,  cudaEventDisableTiming);
        cudaEventCreateWithFlags(&eS2,  cudaEventDisableTiming);
        cudaFuncSetAttribute(k_gemm_m, cudaFuncAttributeMaxDynamicSharedMemorySize, GM_SMEM);
        cudaFuncSetAttribute(k_atb_tc, cudaFuncAttributeMaxDynamicSharedMemorySize, ATB_SMEM);
    }

    const int gb = (N + 63) / 64;
    const int aw = (N * 32 + 255) / 256;
    const int prep_items = 7 * 16384 + N + CKA_TOT;

    float* out = (float*)d_out;
    int off = out_size - N * F;
    if (off < 0) off = 0;

    // ---- prep first (zeroes cnt + cka, splits weights) ---------------------------
    k_prep<<<(prep_items + 255) / 256, 256>>>(W_ir1, W_ir2, W_g1, W_g2, W_d1, W_d2, N);
    cudaEventRecord(eP, 0);

    // ---- CSR on s1 (overlaps G12'), G12' on stream0 (launch idx 3 -> ncu) --------
    cudaStreamWaitEvent(s1, eP, 0);
    k_count<<<(E + 255) / 256, 256, 0, s1>>>(ei, E);
    k_scan1<<<(N + 1023) / 1024, 1024, 0, s1>>>(N);
    k_gemm_m<<<gb, 256, GM_SMEM>>>(x, 0, 1, 0, 2, 2, 0, 0, 0, t0, t2, N);  // G12' raw
    cudaEventRecord(eG12, 0);
    k_fill<<<(E + 255) / 256, 256, 0, s1>>>(ei, E);
    cudaEventRecord(eFill, s1);

    // ---- layer-1 gathers: s1 and s2 in parallel ----------------------------------
    cudaStreamWaitEvent(s1, eG12, 0);
    k_agg_d<<<aw, 256, 0, s1>>>(t0, b_ir1, t1, N, 1);                    // t1 = relu conv
    cudaEventRecord(eIr1, s1);
    cudaStreamWaitEvent(s2, eFill, 0);
    cudaStreamWaitEvent(s2, eG12, 0);
    k_agg_d<<<aw, 256, 0, s2>>>(t2, b_g1, invp, N, 1);                   // invp = relu conv
    cudaEventRecord(eG1, s2);

    // ---- layer-2 GEMMs on stream0 --------------------------------------------------
    cudaStreamWaitEvent(0, eIr1, 0);
    k_gemm_m<<<gb, 256, GM_SMEM>>>(t1, 0, 1, 1, 0, 1, 0, 0, disp, t0, 0, N);   // G3
    cudaEventRecord(eG3, 0);
    cudaStreamWaitEvent(0, eG1, 0);
    k_gemm_m<<<gb, 256, GM_SMEM>>>(invp, 0, 1, 3, 0, 1, 0, 0, disp, t2, 0, N); // G4
    cudaEventRecord(eG4, 0);

    // ---- layer-2 gathers: env on s1, inv on s2 --------------------------------------
    cudaStreamWaitEvent(s1, eG3, 0);
    k_agg<<<aw, 256, 0, s1>>>(t0, b_ir2, envp, N, 2);                    // env = tanh
    cudaEventRecord(eEnv, s1);
    cudaStreamWaitEvent(s2, eG4, 0);
    k_agg<<<aw, 256, 0, s2>>>(t2, b_g2, invp, N, 0);                     // inv
    cudaEventRecord(eInv, s2);

    // ---- CKA moments on s2 (overlap decoder) ----------------------------------------
    cudaStreamWaitEvent(s2, eEnv, 0);
    k_colsum<<<(N + 255) / 256, 128, 0, s2>>>(envp, cka + CKA_SX, N);
    k_atb_tc<<<148, 256, ATB_SMEM, s2>>>(envp, envp, cka + CKA_SXX, N);
    k_colsum<<<(N + 255) / 256, 128, 0, s2>>>(invp, cka + CKA_SY, N);
    k_atb_tc<<<148, 256, ATB_SMEM, s2>>>(envp, invp, cka + CKA_SXY, N);
    k_atb_tc<<<148, 256, ATB_SMEM, s2>>>(invp, invp, cka + CKA_SYY, N);
    cudaEventRecord(eS2, s2);

    // ---- decoder on stream0 ------------------------------------------------------------
    cudaStreamWaitEvent(0, eEnv, 0);
    cudaStreamWaitEvent(0, eInv, 0);
    k_gemm_m<<<gb, 256, GM_SMEM>>>(envp, invp, 2, 4, 0, 1, 0, 0, disp, t0, 0, N); // G5
    cudaEventRecord(eG5, 0);
    cudaStreamWaitEvent(s1, eG5, 0);
    k_agg<<<aw, 256, 0, s1>>>(t0, b_d1, t1, N, 1);                       // v = relu
    cudaEventRecord(eDec1, s1);
    cudaStreamWaitEvent(0, eDec1, 0);
    k_gemm_m<<<gb, 256, GM_SMEM>>>(t1, 0, 1, 6, 0, 1, 0, 0, disp, t0, 0, N);      // G6
    cudaEventRecord(eG6, 0);
    cudaStreamWaitEvent(s1, eG6, 0);
    k_agg_ln<<<aw, 256, 0, s1>>>(t0, b_d2, ln_g, ln_b, out + off, N);    // dec + LN
    cudaEventRecord(eLn, s1);

    // ---- final scalar (disjoint from LN region -> only waits Grams) --------------------
    cudaStreamWaitEvent(0, eS2, 0);
    k_cka<<<1, 256>>>(cka, out, off > 0 ? off : 1, (float)N);
    cudaStreamWaitEvent(0, eLn, 0);   // join fork for capture completeness
}

// round 14
// speedup vs baseline: 1.0592x; 1.0592x over previous
#include <cuda_runtime.h>
#include <cuda_bf16.h>
#include <stdint.h>
#include <math.h>

typedef unsigned int u32;
typedef unsigned short u16;

#define MAXN 100096
#define MAXE 1600000
#define F    128

// ---------------- device scratch ------------------------------------------------
// g_cnt invariant: zero at module load; k_count consumes it; k_zero_cnt (after scan)
// re-zeroes it so every replay sees cnt == 0.
__device__ int   g_cnt[MAXN];
__device__ int   g_rowptr[MAXN + 1];
__device__ int   g_cursor[MAXN];
__device__ int   g_col[MAXE];
__device__ float g_dis[MAXN];

__device__ float g_t0[MAXN * F];
__device__ float g_t1[MAXN * F];
__device__ float g_t2[MAXN * F];
__device__ float g_env[MAXN * F];
__device__ float g_inv[MAXN * F];

// pre-split weights: 7 blocks of [n=128][k=128] bf16 (transposed for B operand)
__device__ __align__(16) u16 g_wh[7 * 16384];
__device__ __align__(16) u16 g_wl[7 * 16384];

// CKA moments
#define CKA_SXX 0
#define CKA_SXY 16384
#define CKA_SYY 32768
#define CKA_SX  49152
#define CKA_SY  49280
#define CKA_TOT 49408
__device__ float g_cka[CKA_TOT];

// ================= helpers ======================================================
__device__ __forceinline__ u32 smem_u32(const void* p) {
    u32 a;
    asm("{ .reg .u64 t; cvta.to.shared.u64 t, %1; cvt.u32.u64 %0, t; }" : "=r"(a) : "l"(p));
    return a;
}
__device__ __forceinline__ void ldm_x4(u32& r0, u32& r1, u32& r2, u32& r3, u32 addr) {
    asm volatile("ldmatrix.sync.aligned.m8n8.x4.shared.b16 {%0,%1,%2,%3}, [%4];"
                 : "=r"(r0), "=r"(r1), "=r"(r2), "=r"(r3) : "r"(addr));
}
__device__ __forceinline__ void mma16816(float* c, const u32* a, u32 b0, u32 b1) {
    asm volatile(
        "mma.sync.aligned.m16n8k16.row.col.f32.bf16.bf16.f32 "
        "{%0,%1,%2,%3}, {%4,%5,%6,%7}, {%8,%9}, {%0,%1,%2,%3};"
        : "+f"(c[0]), "+f"(c[1]), "+f"(c[2]), "+f"(c[3])
        : "r"(a[0]), "r"(a[1]), "r"(a[2]), "r"(a[3]), "r"(b0), "r"(b1));
}
__device__ __forceinline__ u16 f2bf(float x) {
    return __bfloat16_as_ushort(__float2bfloat16_rn(x));
}
__device__ __forceinline__ float bf2f(u16 u) {
    return __bfloat162float(__ushort_as_bfloat16(u));
}

// ---------------- CSR kernels ----------------------------------------------------
__global__ void k_count(const int* __restrict__ ei, int E) {
    int e = blockIdx.x * blockDim.x + threadIdx.x;
    if (e < E) atomicAdd(&g_cnt[ei[E + e]], 1);
}

__global__ __launch_bounds__(1024) void k_scan1(int n) {
    __shared__ int s[1024];
    __shared__ int prevs;
    const int b = blockIdx.x, t = threadIdx.x;
    const int base = b * 1024;
    int acc = 0;
    for (int i = t; i < base; i += 1024) acc += g_cnt[i];
    s[t] = acc;
    __syncthreads();
    for (int o = 512; o > 0; o >>= 1) {
        if (t < o) s[t] += s[t + o];
        __syncthreads();
    }
    if (t == 0) prevs = s[0];
    __syncthreads();
    int prev = prevs;
    __syncthreads();
    int i = base + t;
    int v = (i < n) ? g_cnt[i] : 0;
    s[t] = v;
    __syncthreads();
    for (int o = 1; o < 1024; o <<= 1) {
        int u = (t >= o) ? s[t - o] : 0;
        __syncthreads();
        s[t] += u;
        __syncthreads();
    }
    if (i < n) {
        int ex = prev + s[t] - v;
        g_rowptr[i] = ex;
        g_cursor[i] = ex;
        g_dis[i] = rsqrtf((float)(v + 1));
        if (i == n - 1) g_rowptr[n] = ex + v;
    }
}

__global__ void k_fill(const int* __restrict__ ei, int E) {
    int e = blockIdx.x * blockDim.x + threadIdx.x;
    if (e < E) {
        int src = ei[e];
        int dst = ei[E + e];
        int p = atomicAdd(&g_cursor[dst], 1);
        g_col[p] = src;
    }
}

__global__ void k_zero_cnt(int n) {
    int i = blockIdx.x * blockDim.x + threadIdx.x;
    if (i < n) g_cnt[i] = 0;
}

// ---------------- prep: split weights + zero cka (independent of CSR) ------------
__global__ void k_prep_w(const float* W_ir1, const float* W_ir2, const float* W_g1,
                         const float* W_g2, const float* W_d1, const float* W_d2)
{
    int idx = blockIdx.x * blockDim.x + threadIdx.x;
    if (idx < 7 * 16384) {
        int w = idx >> 14;
        int rem = idx & 16383;
        int nn = rem >> 7;
        int k = rem & 127;
        float v;
        switch (w) {
            case 0: v = W_ir1[k * 128 + nn]; break;
            case 1: v = W_ir2[k * 128 + nn]; break;
            case 2: v = W_g1[k * 128 + nn];  break;
            case 3: v = W_g2[k * 128 + nn];  break;
            case 4: v = W_d1[k * 128 + nn];  break;
            case 5: v = W_d1[(k + 128) * 128 + nn]; break;
            default: v = W_d2[k * 128 + nn]; break;
        }
        u16 h = f2bf(v);
        u16 l = f2bf(v - bf2f(h));
        g_wh[idx] = h;
        g_wl[idx] = l;
        return;
    }
    idx -= 7 * 16384;
    if (idx < CKA_TOT) g_cka[idx] = 0.f;
}

// ---------------- AGG variants ----------------------------------------------------
// y[v] = dis[v]*( sum_{u->v} dis[u]*x[u] + dis[v]*x[v] )
__global__ void k_agg_x(const float* __restrict__ x, float* __restrict__ out, int n)
{
    int gw = (blockIdx.x * blockDim.x + threadIdx.x) >> 5;
    int lane = threadIdx.x & 31;
    if (gw >= n) return;
    const float4* h4 = (const float4*)x;
    float dv = g_dis[gw];
    float4 self = h4[gw * 32 + lane];
    float4 a;
    a.x = dv * self.x; a.y = dv * self.y; a.z = dv * self.z; a.w = dv * self.w;
    int s = g_rowptr[gw], e = g_rowptr[gw + 1];
    int i = s;
    for (; i + 2 <= e; i += 2) {
        int u0 = g_col[i], u1 = g_col[i + 1];
        float d0 = g_dis[u0], d1 = g_dis[u1];
        float4 v0 = __ldg(&h4[u0 * 32 + lane]);
        float4 v1 = __ldg(&h4[u1 * 32 + lane]);
        a.x = fmaf(d0, v0.x, a.x); a.y = fmaf(d0, v0.y, a.y);
        a.z = fmaf(d0, v0.z, a.z); a.w = fmaf(d0, v0.w, a.w);
        a.x = fmaf(d1, v1.x, a.x); a.y = fmaf(d1, v1.y, a.y);
        a.z = fmaf(d1, v1.z, a.z); a.w = fmaf(d1, v1.w, a.w);
    }
    if (i < e) {
        int u = g_col[i];
        float du = g_dis[u];
        float4 v = __ldg(&h4[u * 32 + lane]);
        a.x = fmaf(du, v.x, a.x); a.y = fmaf(du, v.y, a.y);
        a.z = fmaf(du, v.z, a.z); a.w = fmaf(du, v.w, a.w);
    }
    float4 r;
    r.x = dv * a.x; r.y = dv * a.y; r.z = dv * a.z; r.w = dv * a.w;
    ((float4*)out)[gw * 32 + lane] = r;
}

// hp pre-scaled by dis: out[v] = act(dis[v]*(sum hp[u] + hp[v]) + b)
__global__ void k_agg(const float* __restrict__ hp, const float* __restrict__ bias,
                      float* __restrict__ out, int n, int act)
{
    int gw = (blockIdx.x * blockDim.x + threadIdx.x) >> 5;
    int lane = threadIdx.x & 31;
    if (gw >= n) return;
    const float4* h4 = (const float4*)hp;
    float4 a = h4[gw * 32 + lane];
    int s = g_rowptr[gw], e = g_rowptr[gw + 1];
    int i = s;
    for (; i + 2 <= e; i += 2) {
        int u0 = g_col[i], u1 = g_col[i + 1];
        float4 v0 = __ldg(&h4[u0 * 32 + lane]);
        float4 v1 = __ldg(&h4[u1 * 32 + lane]);
        a.x += v0.x + v1.x; a.y += v0.y + v1.y;
        a.z += v0.z + v1.z; a.w += v0.w + v1.w;
    }
    if (i < e) {
        int u = g_col[i];
        float4 v = __ldg(&h4[u * 32 + lane]);
        a.x += v.x; a.y += v.y; a.z += v.z; a.w += v.w;
    }
    float d = g_dis[gw];
    float4 b = ((const float4*)bias)[lane];
    float4 r;
    r.x = fmaf(d, a.x, b.x);
    r.y = fmaf(d, a.y, b.y);
    r.z = fmaf(d, a.z, b.z);
    r.w = fmaf(d, a.w, b.w);
    if (act == 1) {
        r.x = fmaxf(r.x, 0.f); r.y = fmaxf(r.y, 0.f);
        r.z = fmaxf(r.z, 0.f); r.w = fmaxf(r.w, 0.f);
    } else if (act == 2) {
        r.x = tanhf(r.x); r.y = tanhf(r.y);
        r.z = tanhf(r.z); r.w = tanhf(r.w);
    }
    ((float4*)out)[gw * 32 + lane] = r;
}

__global__ void k_agg_ln(const float* __restrict__ hp, const float* __restrict__ bias,
                         const float* __restrict__ lng, const float* __restrict__ lnb,
                         float* __restrict__ out, int n)
{
    int gw = (blockIdx.x * blockDim.x + threadIdx.x) >> 5;
    int lane = threadIdx.x & 31;
    if (gw >= n) return;
    const float4* h4 = (const float4*)hp;
    float4 a = h4[gw * 32 + lane];
    int s = g_rowptr[gw], e = g_rowptr[gw + 1];
    int i = s;
    for (; i + 2 <= e; i += 2) {
        int u0 = g_col[i], u1 = g_col[i + 1];
        float4 v0 = __ldg(&h4[u0 * 32 + lane]);
        float4 v1 = __ldg(&h4[u1 * 32 + lane]);
        a.x += v0.x + v1.x; a.y += v0.y + v1.y;
        a.z += v0.z + v1.z; a.w += v0.w + v1.w;
    }
    if (i < e) {
        int u = g_col[i];
        float4 v = __ldg(&h4[u * 32 + lane]);
        a.x += v.x; a.y += v.y; a.z += v.z; a.w += v.w;
    }
    float d = g_dis[gw];
    float4 b = ((const float4*)bias)[lane];
    float4 v;
    v.x = fmaf(d, a.x, b.x);
    v.y = fmaf(d, a.y, b.y);
    v.z = fmaf(d, a.z, b.z);
    v.w = fmaf(d, a.w, b.w);
    float sum = v.x + v.y + v.z + v.w;
#pragma unroll
    for (int o = 16; o; o >>= 1) sum += __shfl_xor_sync(0xffffffffu, sum, o);
    float mu = sum * (1.f / 128.f);
    float dx = v.x - mu, dy = v.y - mu, dz = v.z - mu, dw = v.w - mu;
    float qq = dx * dx + dy * dy + dz * dz + dw * dw;
#pragma unroll
    for (int o = 16; o; o >>= 1) qq += __shfl_xor_sync(0xffffffffu, qq, o);
    float rs = rsqrtf(qq * (1.f / 128.f) + 1e-5f);
    float4 gg = ((const float4*)lng)[lane];
    float4 bb = ((const float4*)lnb)[lane];
    float* o = out + (size_t)gw * 128 + lane * 4;
    o[0] = dx * rs * gg.x + bb.x;
    o[1] = dy * rs * gg.y + bb.y;
    o[2] = dz * rs * gg.z + bb.z;
    o[3] = dw * rs * gg.w + bb.w;
}

// ---------------- tensor-core GEMM: 64-row tiles, 512 threads, 2 CTAs/SM -----------
// 16 warps, each owns m16 x n32 of the 64x128 tile (16 fp32 accumulators).
#define APITCH 272
#define A64_HI 0
#define A64_LO 17408
#define CPB    144
#define B64_HI 34816
#define B64_LO 53248
#define GM_SMEM 71680

__global__ void __launch_bounds__(512, 2) k_gemm_m(
    const float* __restrict__ A0, const float* __restrict__ A1, int npass,
    int wA, int wB, int nw,
    const float* __restrict__ biasA, const float* __restrict__ biasB,
    const float* __restrict__ dis,
    float* __restrict__ outA, float* __restrict__ outB, int n)
{
    extern __shared__ char sm[];
    const u32 sb = smem_u32(sm);
    const int tid = threadIdx.x;
    const int wid = tid >> 5;          // 0..15
    const int lane = tid & 31;
    const int br = blockIdx.x * 64;

    const int m0 = (wid & 3) * 16;     // 4-way M split
    const int n0 = (wid >> 2) * 32;    // 4-way N split
    const int q = lane >> 3, r8 = lane & 7;
    const u32 aOff = (u32)(m0 + r8 + ((q & 1) << 3)) * APITCH + (u32)(((q >> 1) << 3) << 1);
    const u32 bOff = (u32)(n0 + r8 + ((q >> 1) << 3)) * CPB + (u32)(((q & 1) << 3) << 1);
    const int g4 = lane >> 2, t4 = lane & 3;

    float c[4][4];
#pragma unroll
    for (int j = 0; j < 4; ++j)
#pragma unroll
        for (int k = 0; k < 4; ++k) c[j][k] = 0.f;

    for (int p = 0; p < npass; ++p) {
        const float* A = p ? A1 : A0;
        if (p) __syncthreads();
        // convert A tile [64 m][128 k] fp32 -> bf16 hi/lo
        for (int idx = tid; idx < 4096; idx += 512) {
            int m = idx >> 6;
            int kp = (idx & 63) * 2;
            int row = br + m;
            float2 v = make_float2(0.f, 0.f);
            if (row < n) v = *(const float2*)(A + (size_t)row * 128 + kp);
            u16 hx = f2bf(v.x), hy = f2bf(v.y);
            u16 lx = f2bf(v.x - bf2f(hx)), ly = f2bf(v.y - bf2f(hy));
            u32 o = (u32)m * APITCH + (u32)kp * 2;
            *(u32*)(sm + A64_HI + o) = (u32)hx | ((u32)hy << 16);
            *(u32*)(sm + A64_LO + o) = (u32)lx | ((u32)ly << 16);
        }

        for (int w = 0; w < nw; ++w) {
            int wsel = (nw == 2) ? (w ? wB : wA) : (wA + p);
            const u16* wh = g_wh + (size_t)wsel * 16384;
            const u16* wl = g_wl + (size_t)wsel * 16384;
            for (int ch = 0; ch < 2; ++ch) {
                __syncthreads();
                const int k0 = ch * 64;
                for (int idx = tid; idx < 1024; idx += 512) {
                    int nn = idx >> 3;
                    int v = idx & 7;
                    uint4 h = *(const uint4*)(wh + nn * 128 + k0 + v * 8);
                    uint4 l = *(const uint4*)(wl + nn * 128 + k0 + v * 8);
                    u32 o = (u32)nn * CPB + (u32)v * 16;
                    *(uint4*)(sm + B64_HI + o) = h;
                    *(uint4*)(sm + B64_LO + o) = l;
                }
                __syncthreads();

                const u32 aB[3] = { sb + A64_HI + aOff + (u32)ch * 128,
                                    sb + A64_HI + aOff + (u32)ch * 128,
                                    sb + A64_LO + aOff + (u32)ch * 128 };
                const u32 bB[3] = { sb + B64_HI + bOff, sb + B64_LO + bOff, sb + B64_HI + bOff };
#pragma unroll
                for (int t = 0; t < 3; ++t) {
#pragma unroll
                    for (int kk = 0; kk < 4; ++kk) {
                        u32 a[4];
                        ldm_x4(a[0], a[1], a[2], a[3], aB[t] + (u32)kk * 32);
                        u32 bb[8];
                        ldm_x4(bb[0], bb[1], bb[2], bb[3], bB[t] + (u32)kk * 32);
                        ldm_x4(bb[4], bb[5], bb[6], bb[7], bB[t] + 16 * CPB + (u32)kk * 32);
#pragma unroll
                        for (int ni = 0; ni < 4; ++ni)
                            mma16816(c[ni], a, bb[2 * ni], bb[2 * ni + 1]);
                    }
                }
            }
            if (nw == 2) {
                const float* bias = w ? biasB : biasA;
                float* out = w ? outB : outA;
                int row0 = br + m0 + g4;
                int row1 = row0 + 8;
#pragma unroll
                for (int ni = 0; ni < 4; ++ni) {
                    int col = n0 + ni * 8 + 2 * t4;
                    float bx = bias ? bias[col] : 0.f;
                    float by = bias ? bias[col + 1] : 0.f;
                    float2 v0 = make_float2(c[ni][0] + bx, c[ni][1] + by);
                    float2 v1 = make_float2(c[ni][2] + bx, c[ni][3] + by);
                    if (bias) {
                        v0.x = fmaxf(v0.x, 0.f); v0.y = fmaxf(v0.y, 0.f);
                        v1.x = fmaxf(v1.x, 0.f); v1.y = fmaxf(v1.y, 0.f);
                    }
                    if (row0 < n) *(float2*)(out + (size_t)row0 * 128 + col) = v0;
                    if (row1 < n) *(float2*)(out + (size_t)row1 * 128 + col) = v1;
                }
#pragma unroll
                for (int j = 0; j < 4; ++j)
#pragma unroll
                    for (int k = 0; k < 4; ++k) c[j][k] = 0.f;
            }
        }
    }

    if (nw == 1) {
        int row0 = br + m0 + g4;
        int row1 = row0 + 8;
        if (row0 < n) {
            float d = dis[row0];
#pragma unroll
            for (int ni = 0; ni < 4; ++ni)
                *(float2*)(outA + (size_t)row0 * 128 + n0 + ni * 8 + 2 * t4) =
                    make_float2(d * c[ni][0], d * c[ni][1]);
        }
        if (row1 < n) {
            float d = dis[row1];
#pragma unroll
            for (int ni = 0; ni < 4; ++ni)
                *(float2*)(outA + (size_t)row1 * 128 + n0 + ni * 8 + 2 * t4) =
                    make_float2(d * c[ni][2], d * c[ni][3]);
        }
    }
}

// ---------------- CKA --------------------------------------------------------------
__global__ void k_colsum(const float* __restrict__ X, float* __restrict__ s, int n)
{
    int j = threadIdx.x;
    int r0 = blockIdx.x * 256;
    int r1 = r0 + 256; if (r1 > n) r1 = n;
    float acc = 0.f;
    for (int r = r0; r < r1; ++r) acc += X[r * 128 + j];
    atomicAdd(&s[j], acc);
}

#define TPITCH 272
#define TBYTES (128 * TPITCH)
#define OFF_AHI 0
#define OFF_ALO TBYTES
#define OFF_BHI (2 * TBYTES)
#define OFF_BLO (3 * TBYTES)
#define ATB_SMEM (4 * TBYTES)

__global__ __launch_bounds__(256)
void k_atb_tc(const float* __restrict__ X, const float* __restrict__ Y,
              float* __restrict__ S, int n)
{
    extern __shared__ char sm[];
    const u32 sb = smem_u32(sm);
    const int tid = threadIdx.x;
    const int wid = tid >> 5;
    const int lane = tid & 31;

    const int m0 = (wid & 1) * 64;
    const int n0 = (wid >> 1) * 32;
    const int q = lane >> 3, r8 = lane & 7;
    const u32 aOff = (u32)(m0 + r8 + ((q & 1) << 3)) * TPITCH + (u32)(((q >> 1) << 3) << 1);
    const u32 bOff = (u32)(n0 + r8 + ((q >> 1) << 3)) * TPITCH + (u32)(((q & 1) << 3) << 1);

    float c[4][4][4];
#pragma unroll
    for (int i = 0; i < 4; ++i)
#pragma unroll
        for (int j = 0; j < 4; ++j)
#pragma unroll
            for (int k = 0; k < 4; ++k) c[i][j][k] = 0.f;

    bool first = true;
    for (int r0 = blockIdx.x * 128; r0 < n; r0 += gridDim.x * 128) {
        if (!first) __syncthreads();
        first = false;

        for (int idx = tid; idx < 8192; idx += 256) {
            int rl = idx >> 6;
            int fp = (idx & 63) * 2;
            int row = r0 + rl;
            float2 v = make_float2(0.f, 0.f);
            if (row < n) v = *(const float2*)(X + (size_t)row * 128 + fp);
            u16 hx = f2bf(v.x), hy = f2bf(v.y);
            u16 lx = f2bf(v.x - bf2f(hx)), ly = f2bf(v.y - bf2f(hy));
            u32 o0 = (u32)fp * TPITCH + (u32)rl * 2;
            u32 o1 = o0 + TPITCH;
            *(u16*)(sm + OFF_AHI + o0) = hx;
            *(u16*)(sm + OFF_AHI + o1) = hy;
            *(u16*)(sm + OFF_ALO + o0) = lx;
            *(u16*)(sm + OFF_ALO + o1) = ly;
        }
        for (int idx = tid; idx < 8192; idx += 256) {
            int rl = idx >> 6;
            int fp = (idx & 63) * 2;
            int row = r0 + rl;
            float2 v = make_float2(0.f, 0.f);
            if (row < n) v = *(const float2*)(Y + (size_t)row * 128 + fp);
            u16 hx = f2bf(v.x), hy = f2bf(v.y);
            u16 lx = f2bf(v.x - bf2f(hx)), ly = f2bf(v.y - bf2f(hy));
            u32 o0 = (u32)fp * TPITCH + (u32)rl * 2;
            u32 o1 = o0 + TPITCH;
            *(u16*)(sm + OFF_BHI + o0) = hx;
            *(u16*)(sm + OFF_BHI + o1) = hy;
            *(u16*)(sm + OFF_BLO + o0) = lx;
            *(u16*)(sm + OFF_BLO + o1) = ly;
        }
        __syncthreads();

        const u32 aB[3] = { sb + OFF_AHI + aOff, sb + OFF_AHI + aOff, sb + OFF_ALO + aOff };
        const u32 bB[3] = { sb + OFF_BHI + bOff, sb + OFF_BLO + bOff, sb + OFF_BHI + bOff };
#pragma unroll
        for (int t = 0; t < 3; ++t) {
#pragma unroll
            for (int kk = 0; kk < 8; ++kk) {
                u32 a[4][4];
#pragma unroll
                for (int mi = 0; mi < 4; ++mi)
                    ldm_x4(a[mi][0], a[mi][1], a[mi][2], a[mi][3],
                           aB[t] + (u32)mi * 16 * TPITCH + (u32)kk * 32);
                u32 bb[8];
                ldm_x4(bb[0], bb[1], bb[2], bb[3], bB[t] + (u32)kk * 32);
                ldm_x4(bb[4], bb[5], bb[6], bb[7], bB[t] + 16 * TPITCH + (u32)kk * 32);
#pragma unroll
                for (int mi = 0; mi < 4; ++mi)
#pragma unroll
                    for (int ni = 0; ni < 4; ++ni)
                        mma16816(c[mi][ni], a[mi], bb[2 * ni], bb[2 * ni + 1]);
            }
        }
    }

    const int g = lane >> 2, t4 = lane & 3;
#pragma unroll
    for (int mi = 0; mi < 4; ++mi) {
        int fi0 = m0 + mi * 16 + g;
        int fi1 = fi0 + 8;
#pragma unroll
        for (int ni = 0; ni < 4; ++ni) {
            int fj = n0 + ni * 8 + 2 * t4;
            atomicAdd(&S[fi0 * 128 + fj],     c[mi][ni][0]);
            atomicAdd(&S[fi0 * 128 + fj + 1], c[mi][ni][1]);
            atomicAdd(&S[fi1 * 128 + fj],     c[mi][ni][2]);
            atomicAdd(&S[fi1 * 128 + fj + 1], c[mi][ni][3]);
        }
    }
}

__global__ void k_cka(const float* __restrict__ cka, float* __restrict__ out,
                      int off, float fn)
{
    __shared__ float r0[256], r1[256], r2[256];
    const float* Sxx = cka + CKA_SXX;
    const float* Sxy = cka + CKA_SXY;
    const float* Syy = cka + CKA_SYY;
    const float* sx  = cka + CKA_SX;
    const float* sy  = cka + CKA_SY;
    int t = threadIdx.x;
    float hs = 0.f, nx = 0.f, ny = 0.f;
    float inv_n = 1.f / fn;
    for (int idx = t; idx < 16384; idx += 256) {
        int i = idx >> 7, j = idx & 127;
        float mxi = sx[i] * inv_n, mxj = sx[j] * inv_n;
        float myi = sy[i] * inv_n, myj = sy[j] * inv_n;
        float cxy = Sxy[idx] - fn * mxi * myj;
        float cxx = Sxx[idx] - fn * mxi * mxj;
        float cyy = Syy[idx] - fn * myi * myj;
        hs += cxy * cxy;
        nx += cxx * cxx;
        ny += cyy * cyy;
    }
    r0[t] = hs; r1[t] = nx; r2[t] = ny;
    __syncthreads();
    for (int o = 128; o > 0; o >>= 1) {
        if (t < o) { r0[t] += r0[t + o]; r1[t] += r1[t + o]; r2[t] += r2[t + o]; }
        __syncthreads();
    }
    if (t == 0) {
        float val = r0[0] / (sqrtf(r1[0]) * sqrtf(r2[0]));
        for (int i = 0; i < off; ++i) out[i] = val;
    }
}

// ---------------- host ---------------------------------------------------------------
extern "C" void kernel_launch(void* const* d_in, const int* in_sizes, int n_in,
                              void* d_out, int out_size)
{
    const float* x     = (const float*)d_in[0];
    const int*   ei    = (const int*)  d_in[1];
    const float* W_ir1 = (const float*)d_in[2];
    const float* b_ir1 = (const float*)d_in[3];
    const float* W_ir2 = (const float*)d_in[4];
    const float* b_ir2 = (const float*)d_in[5];
    const float* W_g1  = (const float*)d_in[6];
    const float* b_g1  = (const float*)d_in[7];
    const float* W_g2  = (const float*)d_in[8];
    const float* b_g2  = (const float*)d_in[9];
    const float* W_d1  = (const float*)d_in[10];
    const float* b_d1  = (const float*)d_in[11];
    const float* W_d2  = (const float*)d_in[12];
    const float* b_d2  = (const float*)d_in[13];
    const float* ln_g  = (const float*)d_in[14];
    const float* ln_b  = (const float*)d_in[15];

    const int N = in_sizes[0] / F;
    const int E = in_sizes[1] / 2;

    float *t0, *t1, *t2, *envp, *invp, *disp, *cka;
    cudaGetSymbolAddress((void**)&t0,   g_t0);
    cudaGetSymbolAddress((void**)&t1,   g_t1);
    cudaGetSymbolAddress((void**)&t2,   g_t2);
    cudaGetSymbolAddress((void**)&envp, g_env);
    cudaGetSymbolAddress((void**)&invp, g_inv);
    cudaGetSymbolAddress((void**)&disp, g_dis);
    cudaGetSymbolAddress((void**)&cka,  g_cka);

    static cudaStream_t s1 = 0, s2 = 0;
    static cudaEvent_t eRoot = 0, ePw = 0, eScan = 0, eG12 = 0, eG3 = 0, eG4 = 0,
                       eEnv = 0, eInv = 0, eG5 = 0, eDec1 = 0, eG6 = 0, eLn = 0, eS2 = 0;
    if (!s1) {
        cudaStreamCreateWithFlags(&s1, cudaStreamNonBlocking);
        cudaStreamCreateWithFlags(&s2, cudaStreamNonBlocking);
        cudaEventCreateWithFlags(&eRoot,cudaEventDisableTiming);
        cudaEventCreateWithFlags(&ePw,  cudaEventDisableTiming);
        cudaEventCreateWithFlags(&eScan,cudaEventDisableTiming);
        cudaEventCreateWithFlags(&eG12, cudaEventDisableTiming);
        cudaEventCreateWithFlags(&eG3,  cudaEventDisableTiming);
        cudaEventCreateWithFlags(&eG4,  cudaEventDisableTiming);
        cudaEventCreateWithFlags(&eEnv, cudaEventDisableTiming);
        cudaEventCreateWithFlags(&eInv, cudaEventDisableTiming);
        cudaEventCreateWithFlags(&eG5,  cudaEventDisableTiming);
        cudaEventCreateWithFlags(&eDec1,cudaEventDisableTiming);
        cudaEventCreateWithFlags(&eG6,  cudaEventDisableTiming);
        cudaEventCreateWithFlags(&eLn,  cudaEventDisableTiming);
        cudaEventCreateWithFlags(&eS2,  cudaEventDisableTiming);
        cudaFuncSetAttribute(k_gemm_m, cudaFuncAttributeMaxDynamicSharedMemorySize, GM_SMEM);
        cudaFuncSetAttribute(k_atb_tc, cudaFuncAttributeMaxDynamicSharedMemorySize, ATB_SMEM);
    }

    const int gb = (N + 63) / 64;
    const int aw = (N * 32 + 255) / 256;
    const int pw_items = 7 * 16384 + CKA_TOT;

    float* out = (float*)d_out;
    int off = out_size - N * F;
    if (off < 0) off = 0;

    // ---- root CSR chain on stream0 (origin); fork s2 AFTER first capture op -------
    k_count<<<(E + 255) / 256, 256>>>(ei, E);
    cudaEventRecord(eRoot, 0);                         // legal fork point for s2
    k_scan1<<<(N + 1023) / 1024, 1024>>>(N);
    cudaEventRecord(eScan, 0);
    k_fill<<<(E + 255) / 256, 256>>>(ei, E);
    k_agg_x<<<aw, 256>>>(x, t1, N);                                      // y -> t1

    // ---- prep on s2 (overlaps scan/fill/agg_x); cnt re-zero after scan ------------
    cudaStreamWaitEvent(s2, eRoot, 0);
    k_prep_w<<<(pw_items + 255) / 256, 256, 0, s2>>>(W_ir1, W_ir2, W_g1, W_g2, W_d1, W_d2);
    cudaEventRecord(ePw, s2);
    cudaStreamWaitEvent(s2, eScan, 0);
    k_zero_cnt<<<(N + 255) / 256, 256, 0, s2>>>(N);

    // ---- GEMMs: G12 + G3 on stream0, G4 on s2 -------------------------------------
    cudaStreamWaitEvent(0, ePw, 0);
    k_gemm_m<<<gb, 512, GM_SMEM>>>(t1, 0, 1, 0, 2, 2, b_ir1, b_g1, 0, t0, t2, N);   // G12
    cudaEventRecord(eG12, 0);
    k_gemm_m<<<gb, 512, GM_SMEM>>>(t0, 0, 1, 1, 0, 1, 0, 0, disp, t0, 0, N);        // G3
    cudaEventRecord(eG3, 0);
    cudaStreamWaitEvent(s2, eG12, 0);
    k_gemm_m<<<gb, 512, GM_SMEM, s2>>>(t2, 0, 1, 3, 0, 1, 0, 0, disp, t2, 0, N);    // G4
    cudaEventRecord(eG4, s2);

    // ---- layer-2 gathers: env on s1, inv on s2 --------------------------------------
    cudaStreamWaitEvent(s1, eG3, 0);
    k_agg<<<aw, 256, 0, s1>>>(t0, b_ir2, envp, N, 2);                    // env = tanh
    cudaEventRecord(eEnv, s1);
    k_agg<<<aw, 256, 0, s2>>>(t2, b_g2, invp, N, 0);                     // inv (s2 serial)
    cudaEventRecord(eInv, s2);

    // ---- CKA moments on s2 (overlap decoder) ----------------------------------------
    cudaStreamWaitEvent(s2, eEnv, 0);
    k_colsum<<<(N + 255) / 256, 128, 0, s2>>>(envp, cka + CKA_SX, N);
    k_atb_tc<<<148, 256, ATB_SMEM, s2>>>(envp, envp, cka + CKA_SXX, N);
    k_colsum<<<(N + 255) / 256, 128, 0, s2>>>(invp, cka + CKA_SY, N);
    k_atb_tc<<<148, 256, ATB_SMEM, s2>>>(envp, invp, cka + CKA_SXY, N);
    k_atb_tc<<<148, 256, ATB_SMEM, s2>>>(invp, invp, cka + CKA_SYY, N);
    cudaEventRecord(eS2, s2);

    // ---- decoder on stream0 ------------------------------------------------------------
    cudaStreamWaitEvent(0, eEnv, 0);
    cudaStreamWaitEvent(0, eInv, 0);
    k_gemm_m<<<gb, 512, GM_SMEM>>>(envp, invp, 2, 4, 0, 1, 0, 0, disp, t0, 0, N);   // G5
    cudaEventRecord(eG5, 0);
    cudaStreamWaitEvent(s1, eG5, 0);
    k_agg<<<aw, 256, 0, s1>>>(t0, b_d1, t1, N, 1);                       // v = relu
    cudaEventRecord(eDec1, s1);
    cudaStreamWaitEvent(0, eDec1, 0);
    k_gemm_m<<<gb, 512, GM_SMEM>>>(t1, 0, 1, 6, 0, 1, 0, 0, disp, t0, 0, N);        // G6
    cudaEventRecord(eG6, 0);
    cudaStreamWaitEvent(s1, eG6, 0);
    k_agg_ln<<<aw, 256, 0, s1>>>(t0, b_d2, ln_g, ln_b, out + off, N);    // dec + LN
    cudaEventRecord(eLn, s1);

    // ---- final scalar overlaps aggLN (disjoint out regions) --------------------------
    cudaStreamWaitEvent(0, eS2, 0);
    k_cka<<<1, 256>>>(cka, out, off > 0 ? off : 1, (float)N);
    cudaStreamWaitEvent(0, eLn, 0);   // join fork before graph end
}

// round 15
// speedup vs baseline: 1.3123x; 1.2390x over previous
#include <cuda_runtime.h>
#include <cuda_bf16.h>
#include <stdint.h>
#include <math.h>

typedef unsigned int u32;
typedef unsigned short u16;

#define MAXN 100096
#define MAXE 1600000
#define F    128

// ---------------- device scratch ------------------------------------------------
// g_cnt invariant: zero at module load; k_count consumes it; k_zero_cnt (after scan)
// re-zeroes it so every replay sees cnt == 0.
__device__ int   g_cnt[MAXN];
__device__ int   g_rowptr[MAXN + 1];
__device__ int   g_cursor[MAXN];
__device__ int   g_col[MAXE];
__device__ float g_dis[MAXN];

__device__ float g_t0[MAXN * F];
__device__ float g_t1[MAXN * F];
__device__ float g_t2[MAXN * F];
__device__ float g_env[MAXN * F];
__device__ float g_inv[MAXN * F];

// pre-split weights: 7 blocks of [n=128][k=128] bf16 (transposed for B operand)
__device__ __align__(16) u16 g_wh[7 * 16384];
__device__ __align__(16) u16 g_wl[7 * 16384];

// CKA moments
#define CKA_SXX 0
#define CKA_SXY 16384
#define CKA_SYY 32768
#define CKA_SX  49152
#define CKA_SY  49280
#define CKA_TOT 49408
__device__ float g_cka[CKA_TOT];

// ================= helpers ======================================================
__device__ __forceinline__ u32 smem_u32(const void* p) {
    u32 a;
    asm("{ .reg .u64 t; cvta.to.shared.u64 t, %1; cvt.u32.u64 %0, t; }" : "=r"(a) : "l"(p));
    return a;
}
__device__ __forceinline__ void ldm_x4(u32& r0, u32& r1, u32& r2, u32& r3, u32 addr) {
    asm volatile("ldmatrix.sync.aligned.m8n8.x4.shared.b16 {%0,%1,%2,%3}, [%4];"
                 : "=r"(r0), "=r"(r1), "=r"(r2), "=r"(r3) : "r"(addr));
}
__device__ __forceinline__ void mma16816(float* c, const u32* a, u32 b0, u32 b1) {
    asm volatile(
        "mma.sync.aligned.m16n8k16.row.col.f32.bf16.bf16.f32 "
        "{%0,%1,%2,%3}, {%4,%5,%6,%7}, {%8,%9}, {%0,%1,%2,%3};"
        : "+f"(c[0]), "+f"(c[1]), "+f"(c[2]), "+f"(c[3])
        : "r"(a[0]), "r"(a[1]), "r"(a[2]), "r"(a[3]), "r"(b0), "r"(b1));
}
__device__ __forceinline__ u16 f2bf(float x) {
    return __bfloat16_as_ushort(__float2bfloat16_rn(x));
}
__device__ __forceinline__ float bf2f(u16 u) {
    return __bfloat162float(__ushort_as_bfloat16(u));
}

// ---------------- CSR kernels ----------------------------------------------------
__global__ void k_count(const int* __restrict__ ei, int E) {
    int e = blockIdx.x * blockDim.x + threadIdx.x;
    if (e < E) atomicAdd(&g_cnt[ei[E + e]], 1);
}

__global__ __launch_bounds__(1024) void k_scan1(int n) {
    __shared__ int s[1024];
    __shared__ int prevs;
    const int b = blockIdx.x, t = threadIdx.x;
    const int base = b * 1024;
    int acc = 0;
    for (int i = t; i < base; i += 1024) acc += g_cnt[i];
    s[t] = acc;
    __syncthreads();
    for (int o = 512; o > 0; o >>= 1) {
        if (t < o) s[t] += s[t + o];
        __syncthreads();
    }
    if (t == 0) prevs = s[0];
    __syncthreads();
    int prev = prevs;
    __syncthreads();
    int i = base + t;
    int v = (i < n) ? g_cnt[i] : 0;
    s[t] = v;
    __syncthreads();
    for (int o = 1; o < 1024; o <<= 1) {
        int u = (t >= o) ? s[t - o] : 0;
        __syncthreads();
        s[t] += u;
        __syncthreads();
    }
    if (i < n) {
        int ex = prev + s[t] - v;
        g_rowptr[i] = ex;
        g_cursor[i] = ex;
        g_dis[i] = rsqrtf((float)(v + 1));
        if (i == n - 1) g_rowptr[n] = ex + v;
    }
}

__global__ void k_fill(const int* __restrict__ ei, int E) {
    int e = blockIdx.x * blockDim.x + threadIdx.x;
    if (e < E) {
        int src = ei[e];
        int dst = ei[E + e];
        int p = atomicAdd(&g_cursor[dst], 1);
        g_col[p] = src;
    }
}

__global__ void k_zero_cnt(int n) {
    int i = blockIdx.x * blockDim.x + threadIdx.x;
    if (i < n) g_cnt[i] = 0;
}

// ---------------- prep: split weights + zero cka ----------------------------------
__global__ void k_prep_w(const float* W_ir1, const float* W_ir2, const float* W_g1,
                         const float* W_g2, const float* W_d1, const float* W_d2)
{
    int idx = blockIdx.x * blockDim.x + threadIdx.x;
    if (idx < 7 * 16384) {
        int w = idx >> 14;
        int rem = idx & 16383;
        int nn = rem >> 7;
        int k = rem & 127;
        float v;
        switch (w) {
            case 0: v = W_ir1[k * 128 + nn]; break;
            case 1: v = W_ir2[k * 128 + nn]; break;
            case 2: v = W_g1[k * 128 + nn];  break;
            case 3: v = W_g2[k * 128 + nn];  break;
            case 4: v = W_d1[k * 128 + nn];  break;
            case 5: v = W_d1[(k + 128) * 128 + nn]; break;
            default: v = W_d2[k * 128 + nn]; break;
        }
        u16 h = f2bf(v);
        u16 l = f2bf(v - bf2f(h));
        g_wh[idx] = h;
        g_wl[idx] = l;
        return;
    }
    idx -= 7 * 16384;
    if (idx < CKA_TOT) g_cka[idx] = 0.f;
}

// ---------------- AGG variants ----------------------------------------------------
__global__ void k_agg_x(const float* __restrict__ x, float* __restrict__ out, int n)
{
    int gw = (blockIdx.x * blockDim.x + threadIdx.x) >> 5;
    int lane = threadIdx.x & 31;
    if (gw >= n) return;
    const float4* h4 = (const float4*)x;
    float dv = g_dis[gw];
    float4 self = h4[gw * 32 + lane];
    float4 a;
    a.x = dv * self.x; a.y = dv * self.y; a.z = dv * self.z; a.w = dv * self.w;
    int s = g_rowptr[gw], e = g_rowptr[gw + 1];
    int i = s;
    for (; i + 2 <= e; i += 2) {
        int u0 = g_col[i], u1 = g_col[i + 1];
        float d0 = g_dis[u0], d1 = g_dis[u1];
        float4 v0 = __ldg(&h4[u0 * 32 + lane]);
        float4 v1 = __ldg(&h4[u1 * 32 + lane]);
        a.x = fmaf(d0, v0.x, a.x); a.y = fmaf(d0, v0.y, a.y);
        a.z = fmaf(d0, v0.z, a.z); a.w = fmaf(d0, v0.w, a.w);
        a.x = fmaf(d1, v1.x, a.x); a.y = fmaf(d1, v1.y, a.y);
        a.z = fmaf(d1, v1.z, a.z); a.w = fmaf(d1, v1.w, a.w);
    }
    if (i < e) {
        int u = g_col[i];
        float du = g_dis[u];
        float4 v = __ldg(&h4[u * 32 + lane]);
        a.x = fmaf(du, v.x, a.x); a.y = fmaf(du, v.y, a.y);
        a.z = fmaf(du, v.z, a.z); a.w = fmaf(du, v.w, a.w);
    }
    float4 r;
    r.x = dv * a.x; r.y = dv * a.y; r.z = dv * a.z; r.w = dv * a.w;
    ((float4*)out)[gw * 32 + lane] = r;
}

__global__ void k_agg(const float* __restrict__ hp, const float* __restrict__ bias,
                      float* __restrict__ out, int n, int act)
{
    int gw = (blockIdx.x * blockDim.x + threadIdx.x) >> 5;
    int lane = threadIdx.x & 31;
    if (gw >= n) return;
    const float4* h4 = (const float4*)hp;
    float4 a = h4[gw * 32 + lane];
    int s = g_rowptr[gw], e = g_rowptr[gw + 1];
    int i = s;
    for (; i + 2 <= e; i += 2) {
        int u0 = g_col[i], u1 = g_col[i + 1];
        float4 v0 = __ldg(&h4[u0 * 32 + lane]);
        float4 v1 = __ldg(&h4[u1 * 32 + lane]);
        a.x += v0.x + v1.x; a.y += v0.y + v1.y;
        a.z += v0.z + v1.z; a.w += v0.w + v1.w;
    }
    if (i < e) {
        int u = g_col[i];
        float4 v = __ldg(&h4[u * 32 + lane]);
        a.x += v.x; a.y += v.y; a.z += v.z; a.w += v.w;
    }
    float d = g_dis[gw];
    float4 b = ((const float4*)bias)[lane];
    float4 r;
    r.x = fmaf(d, a.x, b.x);
    r.y = fmaf(d, a.y, b.y);
    r.z = fmaf(d, a.z, b.z);
    r.w = fmaf(d, a.w, b.w);
    if (act == 1) {
        r.x = fmaxf(r.x, 0.f); r.y = fmaxf(r.y, 0.f);
        r.z = fmaxf(r.z, 0.f); r.w = fmaxf(r.w, 0.f);
    } else if (act == 2) {
        r.x = tanhf(r.x); r.y = tanhf(r.y);
        r.z = tanhf(r.z); r.w = tanhf(r.w);
    }
    ((float4*)out)[gw * 32 + lane] = r;
}

__global__ void k_agg_ln(const float* __restrict__ hp, const float* __restrict__ bias,
                         const float* __restrict__ lng, const float* __restrict__ lnb,
                         float* __restrict__ out, int n)
{
    int gw = (blockIdx.x * blockDim.x + threadIdx.x) >> 5;
    int lane = threadIdx.x & 31;
    if (gw >= n) return;
    const float4* h4 = (const float4*)hp;
    float4 a = h4[gw * 32 + lane];
    int s = g_rowptr[gw], e = g_rowptr[gw + 1];
    int i = s;
    for (; i + 2 <= e; i += 2) {
        int u0 = g_col[i], u1 = g_col[i + 1];
        float4 v0 = __ldg(&h4[u0 * 32 + lane]);
        float4 v1 = __ldg(&h4[u1 * 32 + lane]);
        a.x += v0.x + v1.x; a.y += v0.y + v1.y;
        a.z += v0.z + v1.z; a.w += v0.w + v1.w;
    }
    if (i < e) {
        int u = g_col[i];
        float4 v = __ldg(&h4[u * 32 + lane]);
        a.x += v.x; a.y += v.y; a.z += v.z; a.w += v.w;
    }
    float d = g_dis[gw];
    float4 b = ((const float4*)bias)[lane];
    float4 v;
    v.x = fmaf(d, a.x, b.x);
    v.y = fmaf(d, a.y, b.y);
    v.z = fmaf(d, a.z, b.z);
    v.w = fmaf(d, a.w, b.w);
    float sum = v.x + v.y + v.z + v.w;
#pragma unroll
    for (int o = 16; o; o >>= 1) sum += __shfl_xor_sync(0xffffffffu, sum, o);
    float mu = sum * (1.f / 128.f);
    float dx = v.x - mu, dy = v.y - mu, dz = v.z - mu, dw = v.w - mu;
    float qq = dx * dx + dy * dy + dz * dz + dw * dw;
#pragma unroll
    for (int o = 16; o; o >>= 1) qq += __shfl_xor_sync(0xffffffffu, qq, o);
    float rs = rsqrtf(qq * (1.f / 128.f) + 1e-5f);
    float4 gg = ((const float4*)lng)[lane];
    float4 bb = ((const float4*)lnb)[lane];
    float* o = out + (size_t)gw * 128 + lane * 4;
    o[0] = dx * rs * gg.x + bb.x;
    o[1] = dy * rs * gg.y + bb.y;
    o[2] = dz * rs * gg.z + bb.z;
    o[3] = dw * rs * gg.w + bb.w;
}

// ---------------- tensor-core GEMM: 64-row tiles, 512 threads, 2 CTAs/SM -----------
#define APITCH 272
#define A64_HI 0
#define A64_LO 17408
#define CPB    144
#define B64_HI 34816
#define B64_LO 53248
#define GM_SMEM 71680

__global__ void __launch_bounds__(512, 2) k_gemm_m(
    const float* __restrict__ A0, const float* __restrict__ A1, int npass,
    int wA, int wB, int nw,
    const float* __restrict__ biasA, const float* __restrict__ biasB,
    const float* __restrict__ dis,
    float* __restrict__ outA, float* __restrict__ outB, int n)
{
    extern __shared__ char sm[];
    const u32 sb = smem_u32(sm);
    const int tid = threadIdx.x;
    const int wid = tid >> 5;
    const int lane = tid & 31;
    const int br = blockIdx.x * 64;

    const int m0 = (wid & 3) * 16;
    const int n0 = (wid >> 2) * 32;
    const int q = lane >> 3, r8 = lane & 7;
    const u32 aOff = (u32)(m0 + r8 + ((q & 1) << 3)) * APITCH + (u32)(((q >> 1) << 3) << 1);
    const u32 bOff = (u32)(n0 + r8 + ((q >> 1) << 3)) * CPB + (u32)(((q & 1) << 3) << 1);
    const int g4 = lane >> 2, t4 = lane & 3;

    float c[4][4];
#pragma unroll
    for (int j = 0; j < 4; ++j)
#pragma unroll
        for (int k = 0; k < 4; ++k) c[j][k] = 0.f;

    for (int p = 0; p < npass; ++p) {
        const float* A = p ? A1 : A0;
        if (p) __syncthreads();
        for (int idx = tid; idx < 4096; idx += 512) {
            int m = idx >> 6;
            int kp = (idx & 63) * 2;
            int row = br + m;
            float2 v = make_float2(0.f, 0.f);
            if (row < n) v = *(const float2*)(A + (size_t)row * 128 + kp);
            u16 hx = f2bf(v.x), hy = f2bf(v.y);
            u16 lx = f2bf(v.x - bf2f(hx)), ly = f2bf(v.y - bf2f(hy));
            u32 o = (u32)m * APITCH + (u32)kp * 2;
            *(u32*)(sm + A64_HI + o) = (u32)hx | ((u32)hy << 16);
            *(u32*)(sm + A64_LO + o) = (u32)lx | ((u32)ly << 16);
        }

        for (int w = 0; w < nw; ++w) {
            int wsel = (nw == 2) ? (w ? wB : wA) : (wA + p);
            const u16* wh = g_wh + (size_t)wsel * 16384;
            const u16* wl = g_wl + (size_t)wsel * 16384;
            for (int ch = 0; ch < 2; ++ch) {
                __syncthreads();
                const int k0 = ch * 64;
                for (int idx = tid; idx < 1024; idx += 512) {
                    int nn = idx >> 3;
                    int v = idx & 7;
                    uint4 h = *(const uint4*)(wh + nn * 128 + k0 + v * 8);
                    uint4 l = *(const uint4*)(wl + nn * 128 + k0 + v * 8);
                    u32 o = (u32)nn * CPB + (u32)v * 16;
                    *(uint4*)(sm + B64_HI + o) = h;
                    *(uint4*)(sm + B64_LO + o) = l;
                }
                __syncthreads();

                const u32 aHi = sb + A64_HI + aOff + (u32)ch * 128;
                const u32 aLo = sb + A64_LO + aOff + (u32)ch * 128;
                const u32 bHi = sb + B64_HI + bOff;
                const u32 bLo = sb + B64_LO + bOff;
#pragma unroll
                for (int kk = 0; kk < 4; ++kk) {
                    u32 ah[4], al[4], bh[8], bl[8];
                    ldm_x4(ah[0], ah[1], ah[2], ah[3], aHi + (u32)kk * 32);
                    ldm_x4(bh[0], bh[1], bh[2], bh[3], bHi + (u32)kk * 32);
                    ldm_x4(bh[4], bh[5], bh[6], bh[7], bHi + 16 * CPB + (u32)kk * 32);
                    ldm_x4(bl[0], bl[1], bl[2], bl[3], bLo + (u32)kk * 32);
                    ldm_x4(bl[4], bl[5], bl[6], bl[7], bLo + 16 * CPB + (u32)kk * 32);
                    ldm_x4(al[0], al[1], al[2], al[3], aLo + (u32)kk * 32);
#pragma unroll
                    for (int ni = 0; ni < 4; ++ni)
                        mma16816(c[ni], ah, bh[2 * ni], bh[2 * ni + 1]);
#pragma unroll
                    for (int ni = 0; ni < 4; ++ni)
                        mma16816(c[ni], ah, bl[2 * ni], bl[2 * ni + 1]);
#pragma unroll
                    for (int ni = 0; ni < 4; ++ni)
                        mma16816(c[ni], al, bh[2 * ni], bh[2 * ni + 1]);
                }
            }
            if (nw == 2) {
                const float* bias = w ? biasB : biasA;
                float* out = w ? outB : outA;
                int row0 = br + m0 + g4;
                int row1 = row0 + 8;
#pragma unroll
                for (int ni = 0; ni < 4; ++ni) {
                    int col = n0 + ni * 8 + 2 * t4;
                    float bx = bias ? bias[col] : 0.f;
                    float by = bias ? bias[col + 1] : 0.f;
                    float2 v0 = make_float2(c[ni][0] + bx, c[ni][1] + by);
                    float2 v1 = make_float2(c[ni][2] + bx, c[ni][3] + by);
                    if (bias) {
                        v0.x = fmaxf(v0.x, 0.f); v0.y = fmaxf(v0.y, 0.f);
                        v1.x = fmaxf(v1.x, 0.f); v1.y = fmaxf(v1.y, 0.f);
                    }
                    if (row0 < n) *(float2*)(out + (size_t)row0 * 128 + col) = v0;
                    if (row1 < n) *(float2*)(out + (size_t)row1 * 128 + col) = v1;
                }
#pragma unroll
                for (int j = 0; j < 4; ++j)
#pragma unroll
                    for (int k = 0; k < 4; ++k) c[j][k] = 0.f;
            }
        }
    }

    if (nw == 1) {
        int row0 = br + m0 + g4;
        int row1 = row0 + 8;
        if (row0 < n) {
            float d = dis[row0];
#pragma unroll
            for (int ni = 0; ni < 4; ++ni)
                *(float2*)(outA + (size_t)row0 * 128 + n0 + ni * 8 + 2 * t4) =
                    make_float2(d * c[ni][0], d * c[ni][1]);
        }
        if (row1 < n) {
            float d = dis[row1];
#pragma unroll
            for (int ni = 0; ni < 4; ++ni)
                *(float2*)(outA + (size_t)row1 * 128 + n0 + ni * 8 + 2 * t4) =
                    make_float2(d * c[ni][2], d * c[ni][3]);
        }
    }
}

// ---------------- fused CKA Gram kernels ---------------------------------------------
#define TPITCH 272
#define TBYTES (128 * TPITCH)

// atb2: Sxx += X^T X ; Sxy += X^T Y ; sx += colsum(X).  512 thr, 16 warps m32n32.
#define F2_XHI 0
#define F2_XLO TBYTES
#define F2_YHI (2 * TBYTES)
#define F2_YLO (3 * TBYTES)
#define F2_SMEM (4 * TBYTES)

__global__ void __launch_bounds__(512)
k_atb2(const float* __restrict__ X, const float* __restrict__ Y,
       float* __restrict__ Sxx, float* __restrict__ Sxy,
       float* __restrict__ sx, int n)
{
    extern __shared__ char sm[];
    const u32 sb = smem_u32(sm);
    const int tid = threadIdx.x;
    const int wid = tid >> 5;
    const int lane = tid & 31;

    const int m0 = (wid & 3) * 32;
    const int n0 = (wid >> 2) * 32;
    const int q = lane >> 3, r8 = lane & 7;
    const u32 aOff = (u32)(m0 + r8 + ((q & 1) << 3)) * TPITCH + (u32)(((q >> 1) << 3) << 1);
    const u32 bOff = (u32)(n0 + r8 + ((q >> 1) << 3)) * TPITCH + (u32)(((q & 1) << 3) << 1);

    float cxx[2][4][4], cxy[2][4][4];
#pragma unroll
    for (int i = 0; i < 2; ++i)
#pragma unroll
        for (int j = 0; j < 4; ++j)
#pragma unroll
            for (int k = 0; k < 4; ++k) { cxx[i][j][k] = 0.f; cxy[i][j][k] = 0.f; }
    float s0 = 0.f, s1 = 0.f;   // colsum(X) for this thread's fixed feature pair

    bool first = true;
    for (int r0 = blockIdx.x * 128; r0 < n; r0 += gridDim.x * 128) {
        if (!first) __syncthreads();
        first = false;

        for (int idx = tid; idx < 8192; idx += 512) {
            int rl = idx >> 6;
            int fp = (idx & 63) * 2;
            int row = r0 + rl;
            float2 v = make_float2(0.f, 0.f);
            if (row < n) v = *(const float2*)(X + (size_t)row * 128 + fp);
            s0 += v.x; s1 += v.y;
            u16 hx = f2bf(v.x), hy = f2bf(v.y);
            u16 lx = f2bf(v.x - bf2f(hx)), ly = f2bf(v.y - bf2f(hy));
            u32 o0 = (u32)fp * TPITCH + (u32)rl * 2;
            u32 o1 = o0 + TPITCH;
            *(u16*)(sm + F2_XHI + o0) = hx;
            *(u16*)(sm + F2_XHI + o1) = hy;
            *(u16*)(sm + F2_XLO + o0) = lx;
            *(u16*)(sm + F2_XLO + o1) = ly;
        }
        for (int idx = tid; idx < 8192; idx += 512) {
            int rl = idx >> 6;
            int fp = (idx & 63) * 2;
            int row = r0 + rl;
            float2 v = make_float2(0.f, 0.f);
            if (row < n) v = *(const float2*)(Y + (size_t)row * 128 + fp);
            u16 hx = f2bf(v.x), hy = f2bf(v.y);
            u16 lx = f2bf(v.x - bf2f(hx)), ly = f2bf(v.y - bf2f(hy));
            u32 o0 = (u32)fp * TPITCH + (u32)rl * 2;
            u32 o1 = o0 + TPITCH;
            *(u16*)(sm + F2_YHI + o0) = hx;
            *(u16*)(sm + F2_YHI + o1) = hy;
            *(u16*)(sm + F2_YLO + o0) = lx;
            *(u16*)(sm + F2_YLO + o1) = ly;
        }
        __syncthreads();

#pragma unroll
        for (int kk = 0; kk < 8; ++kk) {
            const u32 kb = (u32)kk * 32;
            u32 ah[8], al[8], be[8], bi[8];
            // A frags (X hi/lo, two m16 halves)
            ldm_x4(ah[0], ah[1], ah[2], ah[3], sb + F2_XHI + aOff + kb);
            ldm_x4(ah[4], ah[5], ah[6], ah[7], sb + F2_XHI + aOff + 16 * TPITCH + kb);
            ldm_x4(al[0], al[1], al[2], al[3], sb + F2_XLO + aOff + kb);
            ldm_x4(al[4], al[5], al[6], al[7], sb + F2_XLO + aOff + 16 * TPITCH + kb);
            // term hh
            ldm_x4(be[0], be[1], be[2], be[3], sb + F2_XHI + bOff + kb);
            ldm_x4(be[4], be[5], be[6], be[7], sb + F2_XHI + bOff + 16 * TPITCH + kb);
            ldm_x4(bi[0], bi[1], bi[2], bi[3], sb + F2_YHI + bOff + kb);
            ldm_x4(bi[4], bi[5], bi[6], bi[7], sb + F2_YHI + bOff + 16 * TPITCH + kb);
#pragma unroll
            for (int mi = 0; mi < 2; ++mi)
#pragma unroll
                for (int ni = 0; ni < 4; ++ni) {
                    mma16816(cxx[mi][ni], ah + 4 * mi, be[2 * ni], be[2 * ni + 1]);
                    mma16816(cxy[mi][ni], ah + 4 * mi, bi[2 * ni], bi[2 * ni + 1]);
                }
            // term lh (A lo, B hi — reuse be/bi)
#pragma unroll
            for (int mi = 0; mi < 2; ++mi)
#pragma unroll
                for (int ni = 0; ni < 4; ++ni) {
                    mma16816(cxx[mi][ni], al + 4 * mi, be[2 * ni], be[2 * ni + 1]);
                    mma16816(cxy[mi][ni], al + 4 * mi, bi[2 * ni], bi[2 * ni + 1]);
                }
            // term hl (A hi, B lo)
            ldm_x4(be[0], be[1], be[2], be[3], sb + F2_XLO + bOff + kb);
            ldm_x4(be[4], be[5], be[6], be[7], sb + F2_XLO + bOff + 16 * TPITCH + kb);
            ldm_x4(bi[0], bi[1], bi[2], bi[3], sb + F2_YLO + bOff + kb);
            ldm_x4(bi[4], bi[5], bi[6], bi[7], sb + F2_YLO + bOff + 16 * TPITCH + kb);
#pragma unroll
            for (int mi = 0; mi < 2; ++mi)
#pragma unroll
                for (int ni = 0; ni < 4; ++ni) {
                    mma16816(cxx[mi][ni], ah + 4 * mi, be[2 * ni], be[2 * ni + 1]);
                    mma16816(cxy[mi][ni], ah + 4 * mi, bi[2 * ni], bi[2 * ni + 1]);
                }
        }
    }

    const int g = lane >> 2, t4 = lane & 3;
#pragma unroll
    for (int mi = 0; mi < 2; ++mi) {
        int fi0 = m0 + mi * 16 + g;
        int fi1 = fi0 + 8;
#pragma unroll
        for (int ni = 0; ni < 4; ++ni) {
            int fj = n0 + ni * 8 + 2 * t4;
            atomicAdd(&Sxx[fi0 * 128 + fj],     cxx[mi][ni][0]);
            atomicAdd(&Sxx[fi0 * 128 + fj + 1], cxx[mi][ni][1]);
            atomicAdd(&Sxx[fi1 * 128 + fj],     cxx[mi][ni][2]);
            atomicAdd(&Sxx[fi1 * 128 + fj + 1], cxx[mi][ni][3]);
            atomicAdd(&Sxy[fi0 * 128 + fj],     cxy[mi][ni][0]);
            atomicAdd(&Sxy[fi0 * 128 + fj + 1], cxy[mi][ni][1]);
            atomicAdd(&Sxy[fi1 * 128 + fj],     cxy[mi][ni][2]);
            atomicAdd(&Sxy[fi1 * 128 + fj + 1], cxy[mi][ni][3]);
        }
    }
    int fp = (tid & 63) * 2;
    atomicAdd(&sx[fp],     s0);
    atomicAdd(&sx[fp + 1], s1);
}

// atb1: Syy += Y^T Y ; sy += colsum(Y).  512 thr, 16 warps m32n32.
#define F1_YHI 0
#define F1_YLO TBYTES
#define F1_SMEM (2 * TBYTES)

__global__ void __launch_bounds__(512)
k_atb1(const float* __restrict__ Y, float* __restrict__ Syy,
       float* __restrict__ sy, int n)
{
    extern __shared__ char sm[];
    const u32 sb = smem_u32(sm);
    const int tid = threadIdx.x;
    const int wid = tid >> 5;
    const int lane = tid & 31;

    const int m0 = (wid & 3) * 32;
    const int n0 = (wid >> 2) * 32;
    const int q = lane >> 3, r8 = lane & 7;
    const u32 aOff = (u32)(m0 + r8 + ((q & 1) << 3)) * TPITCH + (u32)(((q >> 1) << 3) << 1);
    const u32 bOff = (u32)(n0 + r8 + ((q >> 1) << 3)) * TPITCH + (u32)(((q & 1) << 3) << 1);

    float cyy[2][4][4];
#pragma unroll
    for (int i = 0; i < 2; ++i)
#pragma unroll
        for (int j = 0; j < 4; ++j)
#pragma unroll
            for (int k = 0; k < 4; ++k) cyy[i][j][k] = 0.f;
    float s0 = 0.f, s1 = 0.f;

    bool first = true;
    for (int r0 = blockIdx.x * 128; r0 < n; r0 += gridDim.x * 128) {
        if (!first) __syncthreads();
        first = false;

        for (int idx = tid; idx < 8192; idx += 512) {
            int rl = idx >> 6;
            int fp = (idx & 63) * 2;
            int row = r0 + rl;
            float2 v = make_float2(0.f, 0.f);
            if (row < n) v = *(const float2*)(Y + (size_t)row * 128 + fp);
            s0 += v.x; s1 += v.y;
            u16 hx = f2bf(v.x), hy = f2bf(v.y);
            u16 lx = f2bf(v.x - bf2f(hx)), ly = f2bf(v.y - bf2f(hy));
            u32 o0 = (u32)fp * TPITCH + (u32)rl * 2;
            u32 o1 = o0 + TPITCH;
            *(u16*)(sm + F1_YHI + o0) = hx;
            *(u16*)(sm + F1_YHI + o1) = hy;
            *(u16*)(sm + F1_YLO + o0) = lx;
            *(u16*)(sm + F1_YLO + o1) = ly;
        }
        __syncthreads();

#pragma unroll
        for (int kk = 0; kk < 8; ++kk) {
            const u32 kb = (u32)kk * 32;
            u32 ah[8], al[8], bh[8], bl[8];
            ldm_x4(ah[0], ah[1], ah[2], ah[3], sb + F1_YHI + aOff + kb);
            ldm_x4(ah[4], ah[5], ah[6], ah[7], sb + F1_YHI + aOff + 16 * TPITCH + kb);
            ldm_x4(al[0], al[1], al[2], al[3], sb + F1_YLO + aOff + kb);
            ldm_x4(al[4], al[5], al[6], al[7], sb + F1_YLO + aOff + 16 * TPITCH + kb);
            ldm_x4(bh[0], bh[1], bh[2], bh[3], sb + F1_YHI + bOff + kb);
            ldm_x4(bh[4], bh[5], bh[6], bh[7], sb + F1_YHI + bOff + 16 * TPITCH + kb);
            ldm_x4(bl[0], bl[1], bl[2], bl[3], sb + F1_YLO + bOff + kb);
            ldm_x4(bl[4], bl[5], bl[6], bl[7], sb + F1_YLO + bOff + 16 * TPITCH + kb);
#pragma unroll
            for (int mi = 0; mi < 2; ++mi)
#pragma unroll
                for (int ni = 0; ni < 4; ++ni) {
                    mma16816(cyy[mi][ni], ah + 4 * mi, bh[2 * ni], bh[2 * ni + 1]);
                    mma16816(cyy[mi][ni], ah + 4 * mi, bl[2 * ni], bl[2 * ni + 1]);
                    mma16816(cyy[mi][ni], al + 4 * mi, bh[2 * ni], bh[2 * ni + 1]);
                }
        }
    }

    const int g = lane >> 2, t4 = lane & 3;
#pragma unroll
    for (int mi = 0; mi < 2; ++mi) {
        int fi0 = m0 + mi * 16 + g;
        int fi1 = fi0 + 8;
#pragma unroll
        for (int ni = 0; ni < 4; ++ni) {
            int fj = n0 + ni * 8 + 2 * t4;
            atomicAdd(&Syy[fi0 * 128 + fj],     cyy[mi][ni][0]);
            atomicAdd(&Syy[fi0 * 128 + fj + 1], cyy[mi][ni][1]);
            atomicAdd(&Syy[fi1 * 128 + fj],     cyy[mi][ni][2]);
            atomicAdd(&Syy[fi1 * 128 + fj + 1], cyy[mi][ni][3]);
        }
    }
    int fp = (tid & 63) * 2;
    atomicAdd(&sy[fp],     s0);
    atomicAdd(&sy[fp + 1], s1);
}

__global__ void k_cka(const float* __restrict__ cka, float* __restrict__ out,
                      int off, float fn)
{
    __shared__ float r0[256], r1[256], r2[256];
    const float* Sxx = cka + CKA_SXX;
    const float* Sxy = cka + CKA_SXY;
    const float* Syy = cka + CKA_SYY;
    const float* sx  = cka + CKA_SX;
    const float* sy  = cka + CKA_SY;
    int t = threadIdx.x;
    float hs = 0.f, nx = 0.f, ny = 0.f;
    float inv_n = 1.f / fn;
    for (int idx = t; idx < 16384; idx += 256) {
        int i = idx >> 7, j = idx & 127;
        float mxi = sx[i] * inv_n, mxj = sx[j] * inv_n;
        float myi = sy[i] * inv_n, myj = sy[j] * inv_n;
        float cxy = Sxy[idx] - fn * mxi * myj;
        float cxx = Sxx[idx] - fn * mxi * mxj;
        float cyy = Syy[idx] - fn * myi * myj;
        hs += cxy * cxy;
        nx += cxx * cxx;
        ny += cyy * cyy;
    }
    r0[t] = hs; r1[t] = nx; r2[t] = ny;
    __syncthreads();
    for (int o = 128; o > 0; o >>= 1) {
        if (t < o) { r0[t] += r0[t + o]; r1[t] += r1[t + o]; r2[t] += r2[t + o]; }
        __syncthreads();
    }
    if (t == 0) {
        float val = r0[0] / (sqrtf(r1[0]) * sqrtf(r2[0]));
        for (int i = 0; i < off; ++i) out[i] = val;
    }
}

// ---------------- host ---------------------------------------------------------------
extern "C" void kernel_launch(void* const* d_in, const int* in_sizes, int n_in,
                              void* d_out, int out_size)
{
    const float* x     = (const float*)d_in[0];
    const int*   ei    = (const int*)  d_in[1];
    const float* W_ir1 = (const float*)d_in[2];
    const float* b_ir1 = (const float*)d_in[3];
    const float* W_ir2 = (const float*)d_in[4];
    const float* b_ir2 = (const float*)d_in[5];
    const float* W_g1  = (const float*)d_in[6];
    const float* b_g1  = (const float*)d_in[7];
    const float* W_g2  = (const float*)d_in[8];
    const float* b_g2  = (const float*)d_in[9];
    const float* W_d1  = (const float*)d_in[10];
    const float* b_d1  = (const float*)d_in[11];
    const float* W_d2  = (const float*)d_in[12];
    const float* b_d2  = (const float*)d_in[13];
    const float* ln_g  = (const float*)d_in[14];
    const float* ln_b  = (const float*)d_in[15];

    const int N = in_sizes[0] / F;
    const int E = in_sizes[1] / 2;

    float *t0, *t1, *t2, *envp, *invp, *disp, *cka;
    cudaGetSymbolAddress((void**)&t0,   g_t0);
    cudaGetSymbolAddress((void**)&t1,   g_t1);
    cudaGetSymbolAddress((void**)&t2,   g_t2);
    cudaGetSymbolAddress((void**)&envp, g_env);
    cudaGetSymbolAddress((void**)&invp, g_inv);
    cudaGetSymbolAddress((void**)&disp, g_dis);
    cudaGetSymbolAddress((void**)&cka,  g_cka);

    static cudaStream_t s1 = 0, s2 = 0;
    static cudaEvent_t eRoot = 0, ePw = 0, eScan = 0, eG12 = 0, eG3 = 0, eG4 = 0,
                       eEnv = 0, eInv = 0, eG5 = 0, eDec1 = 0, eG6 = 0, eLn = 0, eS2 = 0;
    if (!s1) {
        cudaStreamCreateWithFlags(&s1, cudaStreamNonBlocking);
        cudaStreamCreateWithFlags(&s2, cudaStreamNonBlocking);
        cudaEventCreateWithFlags(&eRoot,cudaEventDisableTiming);
        cudaEventCreateWithFlags(&ePw,  cudaEventDisableTiming);
        cudaEventCreateWithFlags(&eScan,cudaEventDisableTiming);
        cudaEventCreateWithFlags(&eG12, cudaEventDisableTiming);
        cudaEventCreateWithFlags(&eG3,  cudaEventDisableTiming);
        cudaEventCreateWithFlags(&eG4,  cudaEventDisableTiming);
        cudaEventCreateWithFlags(&eEnv, cudaEventDisableTiming);
        cudaEventCreateWithFlags(&eInv, cudaEventDisableTiming);
        cudaEventCreateWithFlags(&eG5,  cudaEventDisableTiming);
        cudaEventCreateWithFlags(&eDec1,cudaEventDisableTiming);
        cudaEventCreateWithFlags(&eG6,  cudaEventDisableTiming);
        cudaEventCreateWithFlags(&eLn,  cudaEventDisableTiming);
        cudaEventCreateWithFlags(&eS2,  cudaEventDisableTiming);
        cudaFuncSetAttribute(k_gemm_m, cudaFuncAttributeMaxDynamicSharedMemorySize, GM_SMEM);
        cudaFuncSetAttribute(k_atb2,   cudaFuncAttributeMaxDynamicSharedMemorySize, F2_SMEM);
        cudaFuncSetAttribute(k_atb1,   cudaFuncAttributeMaxDynamicSharedMemorySize, F1_SMEM);
    }

    const int gb = (N + 63) / 64;
    const int aw = (N * 32 + 255) / 256;
    const int pw_items = 7 * 16384 + CKA_TOT;

    float* out = (float*)d_out;
    int off = out_size - N * F;
    if (off < 0) off = 0;

    // ---- root CSR chain on stream0 ---------------------------------------------
    k_count<<<(E + 255) / 256, 256>>>(ei, E);
    cudaEventRecord(eRoot, 0);
    k_scan1<<<(N + 1023) / 1024, 1024>>>(N);
    cudaEventRecord(eScan, 0);
    k_fill<<<(E + 255) / 256, 256>>>(ei, E);
    k_agg_x<<<aw, 256>>>(x, t1, N);                                      // y -> t1

    // ---- prep on s2 (overlaps scan/fill/agg_x); cnt re-zero after scan ------------
    cudaStreamWaitEvent(s2, eRoot, 0);
    k_prep_w<<<(pw_items + 255) / 256, 256, 0, s2>>>(W_ir1, W_ir2, W_g1, W_g2, W_d1, W_d2);
    cudaEventRecord(ePw, s2);
    cudaStreamWaitEvent(s2, eScan, 0);
    k_zero_cnt<<<(N + 255) / 256, 256, 0, s2>>>(N);

    // ---- GEMMs: G12 + G3 on stream0, G4 on s2 -------------------------------------
    cudaStreamWaitEvent(0, ePw, 0);
    k_gemm_m<<<gb, 512, GM_SMEM>>>(t1, 0, 1, 0, 2, 2, b_ir1, b_g1, 0, t0, t2, N);   // G12
    cudaEventRecord(eG12, 0);
    k_gemm_m<<<gb, 512, GM_SMEM>>>(t0, 0, 1, 1, 0, 1, 0, 0, disp, t0, 0, N);        // G3
    cudaEventRecord(eG3, 0);
    cudaStreamWaitEvent(s2, eG12, 0);
    k_gemm_m<<<gb, 512, GM_SMEM, s2>>>(t2, 0, 1, 3, 0, 1, 0, 0, disp, t2, 0, N);    // G4
    cudaEventRecord(eG4, s2);

    // ---- layer-2 gathers: env on s1, inv on s2 --------------------------------------
    cudaStreamWaitEvent(s1, eG3, 0);
    k_agg<<<aw, 256, 0, s1>>>(t0, b_ir2, envp, N, 2);                    // env = tanh
    cudaEventRecord(eEnv, s1);
    k_agg<<<aw, 256, 0, s2>>>(t2, b_g2, invp, N, 0);                     // inv (s2 serial)
    cudaEventRecord(eInv, s2);

    // ---- fused CKA moments on s2 (overlap decoder) ----------------------------------
    k_atb1<<<148, 512, F1_SMEM, s2>>>(invp, cka + CKA_SYY, cka + CKA_SY, N);
    cudaStreamWaitEvent(s2, eEnv, 0);
    k_atb2<<<148, 512, F2_SMEM, s2>>>(envp, invp, cka + CKA_SXX, cka + CKA_SXY,
                                      cka + CKA_SX, N);
    cudaEventRecord(eS2, s2);

    // ---- decoder on stream0 ------------------------------------------------------------
    cudaStreamWaitEvent(0, eEnv, 0);
    cudaStreamWaitEvent(0, eInv, 0);
    k_gemm_m<<<gb, 512, GM_SMEM>>>(envp, invp, 2, 4, 0, 1, 0, 0, disp, t0, 0, N);   // G5
    cudaEventRecord(eG5, 0);
    cudaStreamWaitEvent(s1, eG5, 0);
    k_agg<<<aw, 256, 0, s1>>>(t0, b_d1, t1, N, 1);                       // v = relu
    cudaEventRecord(eDec1, s1);
    cudaStreamWaitEvent(0, eDec1, 0);
    k_gemm_m<<<gb, 512, GM_SMEM>>>(t1, 0, 1, 6, 0, 1, 0, 0, disp, t0, 0, N);        // G6
    cudaEventRecord(eG6, 0);
    cudaStreamWaitEvent(s1, eG6, 0);
    k_agg_ln<<<aw, 256, 0, s1>>>(t0, b_d2, ln_g, ln_b, out + off, N);    // dec + LN
    cudaEventRecord(eLn, s1);

    // ---- final scalar overlaps aggLN (disjoint out regions) --------------------------
    cudaStreamWaitEvent(0, eS2, 0);
    k_cka<<<1, 256>>>(cka, out, off > 0 ? off : 1, (float)N);
    cudaStreamWaitEvent(0, eLn, 0);   // join fork before graph end
}